// round 3
// baseline (speedup 1.0000x reference)
#include <cuda_runtime.h>
#include <math.h>

#define EPSV 1e-5f

constexpr int Bb = 8;
constexpr int NT = 4096;   // tokens (FFT length)
constexpr int Cc = 192;    // input/output channels
constexpr int Hh = 768;    // hidden channels

// scratch: h in [B, H, N] layout (FFT rows contiguous). 96 MB static device array.
__device__ float g_h1[25165824];  // 8*768*4096

// ---------------------------------------------------------------------------
// fc1: h[b,hc,n] = relu(BN(sum_c W1[hc,c] * x[b,n,c]))
// GEMM: M=768 (hc), N=4096 (tokens), K=192. Both operands K-contiguous.
// ---------------------------------------------------------------------------
__global__ __launch_bounds__(256, 2) void fc1_kernel(
    const float* __restrict__ X, const float* __restrict__ W1,
    const float* __restrict__ g1, const float* __restrict__ b1,
    const float* __restrict__ m1, const float* __restrict__ v1)
{
    const int bz = blockIdx.z;
    const int m0 = blockIdx.y * 128;   // hc base
    const int n0 = blockIdx.x * 128;   // token base
    const float* x = X + (size_t)bz * NT * Cc;

    __shared__ float As[16][132];      // W1 tile, [k][m], padded
    __shared__ float Bs[16][132];      // x  tile, [k][n], padded

    float acc[8][8];
#pragma unroll
    for (int i = 0; i < 8; i++)
#pragma unroll
        for (int j = 0; j < 8; j++) acc[i][j] = 0.f;

    const int tid = threadIdx.x;
    const int tr = (tid >> 4) << 3;    // 0..120
    const int tc = (tid & 15) << 3;    // 0..120
    const int lr = tid >> 2;           // 0..63
    const int lc = (tid & 3) << 2;     // 0,4,8,12

    for (int k0 = 0; k0 < Cc; k0 += 16) {
        float4 a0 = *(const float4*)(W1 + (m0 + lr) * Cc + k0 + lc);
        float4 a1 = *(const float4*)(W1 + (m0 + lr + 64) * Cc + k0 + lc);
        float4 b0 = *(const float4*)(x + (size_t)(n0 + lr) * Cc + k0 + lc);
        float4 b1q = *(const float4*)(x + (size_t)(n0 + lr + 64) * Cc + k0 + lc);
        As[lc + 0][lr] = a0.x; As[lc + 1][lr] = a0.y; As[lc + 2][lr] = a0.z; As[lc + 3][lr] = a0.w;
        As[lc + 0][lr + 64] = a1.x; As[lc + 1][lr + 64] = a1.y; As[lc + 2][lr + 64] = a1.z; As[lc + 3][lr + 64] = a1.w;
        Bs[lc + 0][lr] = b0.x; Bs[lc + 1][lr] = b0.y; Bs[lc + 2][lr] = b0.z; Bs[lc + 3][lr] = b0.w;
        Bs[lc + 0][lr + 64] = b1q.x; Bs[lc + 1][lr + 64] = b1q.y; Bs[lc + 2][lr + 64] = b1q.z; Bs[lc + 3][lr + 64] = b1q.w;
        __syncthreads();
#pragma unroll
        for (int k = 0; k < 16; k++) {
            float4 aa0 = *(const float4*)&As[k][tr];
            float4 aa1 = *(const float4*)&As[k][tr + 4];
            float4 bb0 = *(const float4*)&Bs[k][tc];
            float4 bb1 = *(const float4*)&Bs[k][tc + 4];
            float ar[8] = {aa0.x, aa0.y, aa0.z, aa0.w, aa1.x, aa1.y, aa1.z, aa1.w};
            float br[8] = {bb0.x, bb0.y, bb0.z, bb0.w, bb1.x, bb1.y, bb1.z, bb1.w};
#pragma unroll
            for (int i = 0; i < 8; i++)
#pragma unroll
                for (int j = 0; j < 8; j++)
                    acc[i][j] = fmaf(ar[i], br[j], acc[i][j]);
        }
        __syncthreads();
    }

#pragma unroll
    for (int i = 0; i < 8; i++) {
        int hc = m0 + tr + i;
        float sc = g1[hc] * rsqrtf(v1[hc] + EPSV);
        float bi = b1[hc] - m1[hc] * sc;
        float* dst = g_h1 + ((size_t)(bz * Hh + hc)) * NT + n0 + tc;
        float4 o;
        o.x = fmaxf(fmaf(acc[i][0], sc, bi), 0.f);
        o.y = fmaxf(fmaf(acc[i][1], sc, bi), 0.f);
        o.z = fmaxf(fmaf(acc[i][2], sc, bi), 0.f);
        o.w = fmaxf(fmaf(acc[i][3], sc, bi), 0.f);
        *(float4*)dst = o;
        o.x = fmaxf(fmaf(acc[i][4], sc, bi), 0.f);
        o.y = fmaxf(fmaf(acc[i][5], sc, bi), 0.f);
        o.z = fmaxf(fmaf(acc[i][6], sc, bi), 0.f);
        o.w = fmaxf(fmaf(acc[i][7], sc, bi), 0.f);
        *(float4*)(dst + 4) = o;
    }
}

// ---------------------------------------------------------------------------
// FFT(4096) -> per-channel complex mix+relu -> IFFT(4096), in place on g_h1.
// In-place radix-4 DIF forward + exactly-mirrored radix-4 DIT inverse:
// the mix is identical for every frequency bin, so the digit-reversed
// intermediate order never needs to be undone.
// ---------------------------------------------------------------------------
__device__ __forceinline__ float2 cmulf(float2 a, float2 b) {
    return make_float2(a.x * b.x - a.y * b.y, a.x * b.y + a.y * b.x);
}

// W_4096^m for m in [0, 3072), from quarter-period table T[0..1023]
__device__ __forceinline__ float2 twid(const float2* __restrict__ T, int m) {
    float2 w = T[m & 1023];
    int q = m >> 10;
    if (q == 1) return make_float2(w.y, -w.x);    // * e^{-i pi/2}
    if (q == 2) return make_float2(-w.x, -w.y);   // * e^{-i pi}
    return w;
}

__global__ __launch_bounds__(256) void fft_mix_kernel(
    const float* __restrict__ R, const float* __restrict__ Im,
    const float* __restrict__ RB, const float* __restrict__ IB)
{
    __shared__ float2 S[4096];   // 32 KB data
    __shared__ float2 T[1024];   // 8 KB twiddles: W_4096^m = e^{-2pi i m/4096}

    const int tid = threadIdx.x;
    const int row = blockIdx.x;          // b*768 + hc
    const int hc = row % Hh;
    float* data = g_h1 + (size_t)row * NT;

    for (int m = tid; m < 1024; m += 256) {
        float s, c;
        sincospif(-(float)m / 2048.0f, &s, &c);
        T[m] = make_float2(c, s);
    }
    for (int t = tid; t < 4096; t += 256)
        S[t] = make_float2(data[t], 0.f);
    __syncthreads();

    // forward: radix-4 DIF, L = 4096, 1024, 256, 64, 16, 4
#pragma unroll
    for (int ls = 12; ls >= 2; ls -= 2) {
        const int Q = 1 << (ls - 2);
        const int stepw = 1 << (12 - ls);
#pragma unroll
        for (int tt = 0; tt < 4; tt++) {
            int t = tid + tt * 256;
            int j = t & (Q - 1);
            int base = ((t >> (ls - 2)) << ls) | j;
            float2 a = S[base], b = S[base + Q], c = S[base + 2 * Q], d = S[base + 3 * Q];
            float2 apc = make_float2(a.x + c.x, a.y + c.y);
            float2 amc = make_float2(a.x - c.x, a.y - c.y);
            float2 bpd = make_float2(b.x + d.x, b.y + d.y);
            float2 bmd = make_float2(b.x - d.x, b.y - d.y);
            float2 y1 = make_float2(amc.x + bmd.y, amc.y - bmd.x);   // amc - i*bmd
            float2 y3 = make_float2(amc.x - bmd.y, amc.y + bmd.x);   // amc + i*bmd
            float2 y2 = make_float2(apc.x - bpd.x, apc.y - bpd.y);
            int mm = j * stepw;
            S[base] = make_float2(apc.x + bpd.x, apc.y + bpd.y);
            S[base + Q]     = cmulf(twid(T, mm), y1);
            S[base + 2 * Q] = cmulf(twid(T, 2 * mm), y2);
            S[base + 3 * Q] = cmulf(twid(T, 3 * mm), y3);
        }
        __syncthreads();
    }

    // elementwise complex mix + relu (fold ortho 1/sqrt(4096)=1/64 into input)
    const float rd = R[hc * (Hh + 1)];     // diag(r)[hc]
    const float idg = Im[hc * (Hh + 1)];   // diag(i)[hc]
    const float rbv = RB[hc], ibv = IB[hc];
    const float inv = 0.015625f;           // 1/64
    for (int t = tid; t < 4096; t += 256) {
        float2 v = S[t];
        float re = v.x * inv, im2 = v.y * inv;
        float xr = fmaxf(fmaf(rd, re, fmaf(-idg, im2, rbv)), 0.f);
        float xi = fmaxf(fmaf(rd, im2, fmaf(idg, re, ibv)), 0.f);
        S[t] = make_float2(xr, xi);
    }
    __syncthreads();

    // inverse: mirror stages in reverse order: untwiddle (conj) then inverse butterfly
#pragma unroll
    for (int ls = 2; ls <= 12; ls += 2) {
        const int Q = 1 << (ls - 2);
        const int stepw = 1 << (12 - ls);
#pragma unroll
        for (int tt = 0; tt < 4; tt++) {
            int t = tid + tt * 256;
            int j = t & (Q - 1);
            int base = ((t >> (ls - 2)) << ls) | j;
            int mm = j * stepw;
            float2 w1 = twid(T, mm), w2 = twid(T, 2 * mm), w3 = twid(T, 3 * mm);
            w1.y = -w1.y; w2.y = -w2.y; w3.y = -w3.y;   // conjugate
            float2 t0 = S[base];
            float2 t1 = cmulf(w1, S[base + Q]);
            float2 t2 = cmulf(w2, S[base + 2 * Q]);
            float2 t3 = cmulf(w3, S[base + 3 * Q]);
            float2 apc = make_float2(t0.x + t2.x, t0.y + t2.y);
            float2 amc = make_float2(t0.x - t2.x, t0.y - t2.y);
            float2 bpd = make_float2(t1.x + t3.x, t1.y + t3.y);
            float2 bmd = make_float2(t1.x - t3.x, t1.y - t3.y);
            S[base]         = make_float2(apc.x + bpd.x, apc.y + bpd.y);
            S[base + Q]     = make_float2(amc.x - bmd.y, amc.y + bmd.x);  // amc + i*bmd
            S[base + 2 * Q] = make_float2(apc.x - bpd.x, apc.y - bpd.y);
            S[base + 3 * Q] = make_float2(amc.x + bmd.y, amc.y - bmd.x);  // amc - i*bmd
        }
        __syncthreads();
    }

    for (int t = tid; t < 4096; t += 256)
        data[t] = S[t].x * inv;
}

// ---------------------------------------------------------------------------
// fc2: y[b,n,c] = BN(sum_h h[b,h,n] * W2[c,h])
// GEMM: M=4096 (tokens), N=192 (c), K=768. A[k][m] m-contiguous (direct tile).
// ---------------------------------------------------------------------------
__global__ __launch_bounds__(256, 2) void fc2_kernel(
    const float* __restrict__ W2,
    const float* __restrict__ g2, const float* __restrict__ b2,
    const float* __restrict__ m2, const float* __restrict__ v2,
    float* __restrict__ Y)
{
    const int bz = blockIdx.z;
    const int m0 = blockIdx.x * 128;   // token base
    const int n0 = blockIdx.y * 64;    // channel base
    const float* A = g_h1 + (size_t)bz * Hh * NT;   // [H][NT]

    __shared__ float As[16][128];
    __shared__ float Bs[16][68];

    float acc[8][4];
#pragma unroll
    for (int i = 0; i < 8; i++)
#pragma unroll
        for (int j = 0; j < 4; j++) acc[i][j] = 0.f;

    const int tid = threadIdx.x;
    const int tr = (tid >> 4) << 3;    // 0..120 token offset
    const int tc = (tid & 15) << 2;    // 0..60  channel offset
    const int alr = tid >> 4;          // 0..15 (k row)
    const int alc = (tid & 15) << 3;   // 0..120
    const int blr = tid >> 2;          // 0..63 (c row)
    const int blc = (tid & 3) << 2;    // 0,4,8,12

    for (int k0 = 0; k0 < Hh; k0 += 16) {
        float4 a0 = *(const float4*)(A + (size_t)(k0 + alr) * NT + m0 + alc);
        float4 a1 = *(const float4*)(A + (size_t)(k0 + alr) * NT + m0 + alc + 4);
        float4 w = *(const float4*)(W2 + (n0 + blr) * Hh + k0 + blc);
        *(float4*)&As[alr][alc] = a0;
        *(float4*)&As[alr][alc + 4] = a1;
        Bs[blc + 0][blr] = w.x; Bs[blc + 1][blr] = w.y; Bs[blc + 2][blr] = w.z; Bs[blc + 3][blr] = w.w;
        __syncthreads();
#pragma unroll
        for (int k = 0; k < 16; k++) {
            float4 aa0 = *(const float4*)&As[k][tr];
            float4 aa1 = *(const float4*)&As[k][tr + 4];
            float4 bb = *(const float4*)&Bs[k][tc];
            float ar[8] = {aa0.x, aa0.y, aa0.z, aa0.w, aa1.x, aa1.y, aa1.z, aa1.w};
            float br[4] = {bb.x, bb.y, bb.z, bb.w};
#pragma unroll
            for (int i = 0; i < 8; i++)
#pragma unroll
                for (int j = 0; j < 4; j++)
                    acc[i][j] = fmaf(ar[i], br[j], acc[i][j]);
        }
        __syncthreads();
    }

    float sc[4], bi[4];
#pragma unroll
    for (int j = 0; j < 4; j++) {
        int c = n0 + tc + j;
        sc[j] = g2[c] * rsqrtf(v2[c] + EPSV);
        bi[j] = b2[c] - m2[c] * sc[j];
    }
#pragma unroll
    for (int i = 0; i < 8; i++) {
        int token = m0 + tr + i;
        float4 o;
        o.x = fmaf(acc[i][0], sc[0], bi[0]);
        o.y = fmaf(acc[i][1], sc[1], bi[1]);
        o.z = fmaf(acc[i][2], sc[2], bi[2]);
        o.w = fmaf(acc[i][3], sc[3], bi[3]);
        *(float4*)(Y + ((size_t)bz * NT + token) * Cc + n0 + tc) = o;
    }
}

// ---------------------------------------------------------------------------
extern "C" void kernel_launch(void* const* d_in, const int* in_sizes, int n_in,
                              void* d_out, int out_size) {
    const float* x  = (const float*)d_in[0];
    const float* W1 = (const float*)d_in[1];
    const float* g1 = (const float*)d_in[2];
    const float* b1 = (const float*)d_in[3];
    const float* m1 = (const float*)d_in[4];
    const float* v1 = (const float*)d_in[5];
    const float* r  = (const float*)d_in[6];
    const float* im = (const float*)d_in[7];
    const float* rb = (const float*)d_in[8];
    const float* ib = (const float*)d_in[9];
    const float* W2 = (const float*)d_in[10];
    const float* g2 = (const float*)d_in[11];
    const float* b2 = (const float*)d_in[12];
    const float* m2 = (const float*)d_in[13];
    const float* v2 = (const float*)d_in[14];
    float* out = (float*)d_out;

    fc1_kernel<<<dim3(32, 6, 8), 256>>>(x, W1, g1, b1, m1, v1);
    fft_mix_kernel<<<Bb * Hh, 256>>>(r, im, rb, ib);
    fc2_kernel<<<dim3(32, 3, 8), 256>>>(W2, g2, b2, m2, v2, out);
}

// round 5
// speedup vs baseline: 1.4544x; 1.4544x over previous
#include <cuda_runtime.h>
#include <math.h>

#define EPSV 1e-5f

constexpr int Bb = 8;
constexpr int NT = 4096;   // tokens (FFT length)
constexpr int Cc = 192;    // input/output channels
constexpr int Hh = 768;    // hidden channels

// scratch: h in [B, H, N] layout (FFT rows contiguous). 96 MB static device array.
__device__ float g_h1[25165824];  // 8*768*4096

// ---------------------------------------------------------------------------
// fc1: h[b,hc,n] = relu(BN(sum_c W1[hc,c] * x[b,n,c]))
// GEMM: M=768 (hc), N=4096 (tokens), K=192. Both operands K-contiguous.
// ---------------------------------------------------------------------------
__global__ __launch_bounds__(256, 2) void fc1_kernel(
    const float* __restrict__ X, const float* __restrict__ W1,
    const float* __restrict__ g1, const float* __restrict__ b1,
    const float* __restrict__ m1, const float* __restrict__ v1)
{
    const int bz = blockIdx.z;
    const int m0 = blockIdx.y * 128;   // hc base
    const int n0 = blockIdx.x * 128;   // token base
    const float* x = X + (size_t)bz * NT * Cc;

    __shared__ float As[16][132];      // W1 tile, [k][m], padded
    __shared__ float Bs[16][132];      // x  tile, [k][n], padded

    float acc[8][8];
#pragma unroll
    for (int i = 0; i < 8; i++)
#pragma unroll
        for (int j = 0; j < 8; j++) acc[i][j] = 0.f;

    const int tid = threadIdx.x;
    const int tr = (tid >> 4) << 3;    // 0..120
    const int tc = (tid & 15) << 3;    // 0..120
    const int lr = tid >> 2;           // 0..63
    const int lc = (tid & 3) << 2;     // 0,4,8,12

    for (int k0 = 0; k0 < Cc; k0 += 16) {
        float4 a0 = *(const float4*)(W1 + (m0 + lr) * Cc + k0 + lc);
        float4 a1 = *(const float4*)(W1 + (m0 + lr + 64) * Cc + k0 + lc);
        float4 b0 = *(const float4*)(x + (size_t)(n0 + lr) * Cc + k0 + lc);
        float4 b1q = *(const float4*)(x + (size_t)(n0 + lr + 64) * Cc + k0 + lc);
        As[lc + 0][lr] = a0.x; As[lc + 1][lr] = a0.y; As[lc + 2][lr] = a0.z; As[lc + 3][lr] = a0.w;
        As[lc + 0][lr + 64] = a1.x; As[lc + 1][lr + 64] = a1.y; As[lc + 2][lr + 64] = a1.z; As[lc + 3][lr + 64] = a1.w;
        Bs[lc + 0][lr] = b0.x; Bs[lc + 1][lr] = b0.y; Bs[lc + 2][lr] = b0.z; Bs[lc + 3][lr] = b0.w;
        Bs[lc + 0][lr + 64] = b1q.x; Bs[lc + 1][lr + 64] = b1q.y; Bs[lc + 2][lr + 64] = b1q.z; Bs[lc + 3][lr + 64] = b1q.w;
        __syncthreads();
#pragma unroll
        for (int k = 0; k < 16; k++) {
            float4 aa0 = *(const float4*)&As[k][tr];
            float4 aa1 = *(const float4*)&As[k][tr + 4];
            float4 bb0 = *(const float4*)&Bs[k][tc];
            float4 bb1 = *(const float4*)&Bs[k][tc + 4];
            float ar[8] = {aa0.x, aa0.y, aa0.z, aa0.w, aa1.x, aa1.y, aa1.z, aa1.w};
            float br[8] = {bb0.x, bb0.y, bb0.z, bb0.w, bb1.x, bb1.y, bb1.z, bb1.w};
#pragma unroll
            for (int i = 0; i < 8; i++)
#pragma unroll
                for (int j = 0; j < 8; j++)
                    acc[i][j] = fmaf(ar[i], br[j], acc[i][j]);
        }
        __syncthreads();
    }

#pragma unroll
    for (int i = 0; i < 8; i++) {
        int hc = m0 + tr + i;
        float sc = g1[hc] * rsqrtf(v1[hc] + EPSV);
        float bi = b1[hc] - m1[hc] * sc;
        float* dst = g_h1 + ((size_t)(bz * Hh + hc)) * NT + n0 + tc;
        float4 o;
        o.x = fmaxf(fmaf(acc[i][0], sc, bi), 0.f);
        o.y = fmaxf(fmaf(acc[i][1], sc, bi), 0.f);
        o.z = fmaxf(fmaf(acc[i][2], sc, bi), 0.f);
        o.w = fmaxf(fmaf(acc[i][3], sc, bi), 0.f);
        *(float4*)dst = o;
        o.x = fmaxf(fmaf(acc[i][4], sc, bi), 0.f);
        o.y = fmaxf(fmaf(acc[i][5], sc, bi), 0.f);
        o.z = fmaxf(fmaf(acc[i][6], sc, bi), 0.f);
        o.w = fmaxf(fmaf(acc[i][7], sc, bi), 0.f);
        *(float4*)(dst + 4) = o;
    }
}

// ---------------------------------------------------------------------------
// FFT(4096) -> per-channel complex mix+relu -> IFFT(4096), in place on g_h1.
// Fused radix-16 passes (two radix-4 stages per smem round trip): forward DIF
// stages (4096,1024),(256,64),(16,4); inverse mirrors exactly, so the
// digit-reversed intermediate ordering never needs to be undone (the mix is
// identical for every frequency bin).
// Data array is XOR-swizzled (i ^ ((i>>4)&15)) so every pass's access pattern
// is a permutation of a 16-aligned block per 16-lane LDS.64 phase ->
// conflict-free for all strides including the final contiguous-16 pass.
// ---------------------------------------------------------------------------
__device__ __forceinline__ float2 cmulf(float2 a, float2 b) {
    return make_float2(a.x * b.x - a.y * b.y, a.x * b.y + a.y * b.x);
}
__device__ __forceinline__ float2 cadd(float2 a, float2 b) { return make_float2(a.x + b.x, a.y + b.y); }
__device__ __forceinline__ float2 csub(float2 a, float2 b) { return make_float2(a.x - b.x, a.y - b.y); }

#define SWZ(i) ((i) ^ (((i) >> 4) & 15))

// W_4096^m for m in [0, 3072), from quarter-period table T[0..1023]
__device__ __forceinline__ float2 twid(const float2* __restrict__ T, int m) {
    float2 w = T[m & 1023];
    int q = m >> 10;
    if (q == 1) return make_float2(w.y, -w.x);    // * e^{-i pi/2}
    if (q == 2) return make_float2(-w.x, -w.y);   // * e^{-i pi}
    return w;
}
__device__ __forceinline__ float2 twidc(const float2* __restrict__ T, int m) {
    float2 w = twid(T, m);
    return make_float2(w.x, -w.y);                // conjugate
}

__global__ __launch_bounds__(256) void fft_mix_kernel(
    const float* __restrict__ R, const float* __restrict__ Im,
    const float* __restrict__ RB, const float* __restrict__ IB)
{
    __shared__ float2 S[4096];   // 32 KB data (swizzled indexing)
    __shared__ float2 T[1024];   // 8 KB twiddles: W_4096^m = e^{-2pi i m/4096}

    const int tid = threadIdx.x;
    const int row = blockIdx.x;          // b*768 + hc
    const int hc = row % Hh;
    float* data = g_h1 + (size_t)row * NT;

    for (int m = tid; m < 1024; m += 256) {
        float s, c;
        sincospif(-(float)m / 2048.0f, &s, &c);
        T[m] = make_float2(c, s);
    }
    for (int t = tid; t < 4096; t += 256)
        S[SWZ(t)] = make_float2(data[t], 0.f);
    __syncthreads();

    // ---- forward: 3 fused passes, each = DIF stage 2^ls then 2^(ls-2) ----
#pragma unroll
    for (int ls = 12; ls >= 4; ls -= 4) {
        const int Q  = 1 << (ls - 2);
        const int Q4 = 1 << (ls - 4);
        const int stepw  = 1 << (12 - ls);
        const int stepw4 = stepw << 2;
        const int j = tid & (Q4 - 1);
        const int base = (tid >> (ls - 4)) << ls;

        float2 X[4][4];
#pragma unroll
        for (int q = 0; q < 4; q++)
#pragma unroll
            for (int p = 0; p < 4; p++)
                X[q][p] = S[SWZ(base + j + p * Q4 + q * Q)];

        // stage at size 2^ls: butterfly over q, twiddle exp (j+p*Q4)*stepw
#pragma unroll
        for (int p = 0; p < 4; p++) {
            float2 a = X[0][p], b = X[1][p], c = X[2][p], d = X[3][p];
            float2 apc = cadd(a, c), amc = csub(a, c);
            float2 bpd = cadd(b, d), bmd = csub(b, d);
            int e = (j + p * Q4) * stepw;
            X[0][p] = cadd(apc, bpd);
            X[1][p] = cmulf(twid(T, e),     make_float2(amc.x + bmd.y, amc.y - bmd.x));
            X[2][p] = cmulf(twid(T, 2 * e), csub(apc, bpd));
            X[3][p] = cmulf(twid(T, 3 * e), make_float2(amc.x - bmd.y, amc.y + bmd.x));
        }
        // stage at size 2^(ls-2): butterfly over p, twiddle exp j*stepw4
        {
            int e2 = j * stepw4;
            float2 w1 = twid(T, e2), w2 = twid(T, 2 * e2), w3 = twid(T, 3 * e2);
#pragma unroll
            for (int q = 0; q < 4; q++) {
                float2 a = X[q][0], b = X[q][1], c = X[q][2], d = X[q][3];
                float2 apc = cadd(a, c), amc = csub(a, c);
                float2 bpd = cadd(b, d), bmd = csub(b, d);
                X[q][0] = cadd(apc, bpd);
                X[q][1] = cmulf(w1, make_float2(amc.x + bmd.y, amc.y - bmd.x));
                X[q][2] = cmulf(w2, csub(apc, bpd));
                X[q][3] = cmulf(w3, make_float2(amc.x - bmd.y, amc.y + bmd.x));
            }
        }
        __syncthreads();   // writes below go to exactly the slots this thread read
#pragma unroll
        for (int q = 0; q < 4; q++)
#pragma unroll
            for (int p = 0; p < 4; p++)
                S[SWZ(base + j + p * Q4 + q * Q)] = X[q][p];
        __syncthreads();
    }

    // ---- elementwise complex mix + relu (fold ortho 1/64 into input) ----
    const float rd  = R[hc * (Hh + 1)];    // diag(r)[hc]
    const float idg = Im[hc * (Hh + 1)];   // diag(i)[hc]
    const float rbv = RB[hc], ibv = IB[hc];
    const float inv = 0.015625f;           // 1/64
    for (int t = tid; t < 4096; t += 256) {
        float2 v = S[SWZ(t)];
        float re = v.x * inv, im2 = v.y * inv;
        float xr = fmaxf(fmaf(rd, re, fmaf(-idg, im2, rbv)), 0.f);
        float xi = fmaxf(fmaf(rd, im2, fmaf(idg, re, ibv)), 0.f);
        S[SWZ(t)] = make_float2(xr, xi);
    }
    __syncthreads();

    // ---- inverse: 3 fused passes, each = inv stage 2^(ls-2) then 2^ls ----
#pragma unroll
    for (int ls = 4; ls <= 12; ls += 4) {
        const int Q  = 1 << (ls - 2);
        const int Q4 = 1 << (ls - 4);
        const int stepw  = 1 << (12 - ls);
        const int stepw4 = stepw << 2;
        const int j = tid & (Q4 - 1);
        const int base = (tid >> (ls - 4)) << ls;

        float2 X[4][4];
#pragma unroll
        for (int q = 0; q < 4; q++)
#pragma unroll
            for (int p = 0; p < 4; p++)
                X[q][p] = S[SWZ(base + j + p * Q4 + q * Q)];

        // inverse of stage 2^(ls-2): untwiddle over p (conj), inverse butterfly
        {
            int e2 = j * stepw4;
            float2 w1 = twidc(T, e2), w2 = twidc(T, 2 * e2), w3 = twidc(T, 3 * e2);
#pragma unroll
            for (int q = 0; q < 4; q++) {
                float2 a = X[q][0];
                float2 b = cmulf(w1, X[q][1]);
                float2 c = cmulf(w2, X[q][2]);
                float2 d = cmulf(w3, X[q][3]);
                float2 apc = cadd(a, c), amc = csub(a, c);
                float2 bpd = cadd(b, d), bmd = csub(b, d);
                X[q][0] = cadd(apc, bpd);
                X[q][1] = make_float2(amc.x - bmd.y, amc.y + bmd.x);  // amc + i*bmd
                X[q][2] = csub(apc, bpd);
                X[q][3] = make_float2(amc.x + bmd.y, amc.y - bmd.x);  // amc - i*bmd
            }
        }
        // inverse of stage 2^ls: untwiddle over q (conj), inverse butterfly
#pragma unroll
        for (int p = 0; p < 4; p++) {
            int e = (j + p * Q4) * stepw;
            float2 a = X[0][p];
            float2 b = cmulf(twidc(T, e),     X[1][p]);
            float2 c = cmulf(twidc(T, 2 * e), X[2][p]);
            float2 d = cmulf(twidc(T, 3 * e), X[3][p]);
            float2 apc = cadd(a, c), amc = csub(a, c);
            float2 bpd = cadd(b, d), bmd = csub(b, d);
            X[0][p] = cadd(apc, bpd);
            X[1][p] = make_float2(amc.x - bmd.y, amc.y + bmd.x);
            X[2][p] = csub(apc, bpd);
            X[3][p] = make_float2(amc.x + bmd.y, amc.y - bmd.x);
        }
        __syncthreads();
#pragma unroll
        for (int q = 0; q < 4; q++)
#pragma unroll
            for (int p = 0; p < 4; p++)
                S[SWZ(base + j + p * Q4 + q * Q)] = X[q][p];
        __syncthreads();
    }

    for (int t = tid; t < 4096; t += 256)
        data[t] = S[SWZ(t)].x * inv;
}

// ---------------------------------------------------------------------------
// fc2: y[b,n,c] = BN(sum_h h[b,h,n] * W2[c,h])
// GEMM: M=4096 (tokens), N=192 (c), K=768. A[k][m] m-contiguous.
// 128 threads, 128x64 tile, 8x8 accumulators -> 4 FMA per LDS word
// (same LDS/FMA equilibrium as fc1; old version was 2.67 and LDS-bound).
// ---------------------------------------------------------------------------
__global__ __launch_bounds__(128, 4) void fc2_kernel(
    const float* __restrict__ W2,
    const float* __restrict__ g2, const float* __restrict__ b2,
    const float* __restrict__ m2, const float* __restrict__ v2,
    float* __restrict__ Y)
{
    const int bz = blockIdx.z;
    const int m0 = blockIdx.x * 128;   // token base
    const int n0 = blockIdx.y * 64;    // channel base
    const float* A = g_h1 + (size_t)bz * Hh * NT;   // [H][NT]

    __shared__ float As[16][128];
    __shared__ float Bs[16][72];

    float acc[8][8];
#pragma unroll
    for (int i = 0; i < 8; i++)
#pragma unroll
        for (int j = 0; j < 8; j++) acc[i][j] = 0.f;

    const int tid = threadIdx.x;
    const int tr = (tid >> 3) << 3;    // 0..120 token offset
    const int tc = (tid & 7) << 3;     // 0..56  channel offset
    const int alr = tid >> 3;          // 0..15 (k row)
    const int alc = (tid & 7) << 4;    // 0..112 (m col, 16 floats each)
    const int blr = tid >> 1;          // 0..63 (c row)
    const int blc = (tid & 1) << 3;    // 0 or 8 (k offset)

    for (int k0 = 0; k0 < Hh; k0 += 16) {
        const float* ap = A + (size_t)(k0 + alr) * NT + m0 + alc;
        float4 a0 = *(const float4*)(ap + 0);
        float4 a1 = *(const float4*)(ap + 4);
        float4 a2 = *(const float4*)(ap + 8);
        float4 a3 = *(const float4*)(ap + 12);
        const float* wp = W2 + (n0 + blr) * Hh + k0 + blc;
        float4 w0 = *(const float4*)(wp + 0);
        float4 w1 = *(const float4*)(wp + 4);
        *(float4*)&As[alr][alc + 0]  = a0;
        *(float4*)&As[alr][alc + 4]  = a1;
        *(float4*)&As[alr][alc + 8]  = a2;
        *(float4*)&As[alr][alc + 12] = a3;
        Bs[blc + 0][blr] = w0.x; Bs[blc + 1][blr] = w0.y;
        Bs[blc + 2][blr] = w0.z; Bs[blc + 3][blr] = w0.w;
        Bs[blc + 4][blr] = w1.x; Bs[blc + 5][blr] = w1.y;
        Bs[blc + 6][blr] = w1.z; Bs[blc + 7][blr] = w1.w;
        __syncthreads();
#pragma unroll
        for (int k = 0; k < 16; k++) {
            float4 aa0 = *(const float4*)&As[k][tr];
            float4 aa1 = *(const float4*)&As[k][tr + 4];
            float4 bb0 = *(const float4*)&Bs[k][tc];
            float4 bb1 = *(const float4*)&Bs[k][tc + 4];
            float ar[8] = {aa0.x, aa0.y, aa0.z, aa0.w, aa1.x, aa1.y, aa1.z, aa1.w};
            float br[8] = {bb0.x, bb0.y, bb0.z, bb0.w, bb1.x, bb1.y, bb1.z, bb1.w};
#pragma unroll
            for (int i = 0; i < 8; i++)
#pragma unroll
                for (int j = 0; j < 8; j++)
                    acc[i][j] = fmaf(ar[i], br[j], acc[i][j]);
        }
        __syncthreads();
    }

    float sc[8], bi[8];
#pragma unroll
    for (int j = 0; j < 8; j++) {
        int c = n0 + tc + j;
        sc[j] = g2[c] * rsqrtf(v2[c] + EPSV);
        bi[j] = b2[c] - m2[c] * sc[j];
    }
#pragma unroll
    for (int i = 0; i < 8; i++) {
        int token = m0 + tr + i;
        float* dst = Y + ((size_t)bz * NT + token) * Cc + n0 + tc;
        float4 o;
        o.x = fmaf(acc[i][0], sc[0], bi[0]);
        o.y = fmaf(acc[i][1], sc[1], bi[1]);
        o.z = fmaf(acc[i][2], sc[2], bi[2]);
        o.w = fmaf(acc[i][3], sc[3], bi[3]);
        *(float4*)dst = o;
        o.x = fmaf(acc[i][4], sc[4], bi[4]);
        o.y = fmaf(acc[i][5], sc[5], bi[5]);
        o.z = fmaf(acc[i][6], sc[6], bi[6]);
        o.w = fmaf(acc[i][7], sc[7], bi[7]);
        *(float4*)(dst + 4) = o;
    }
}

// ---------------------------------------------------------------------------
extern "C" void kernel_launch(void* const* d_in, const int* in_sizes, int n_in,
                              void* d_out, int out_size) {
    const float* x  = (const float*)d_in[0];
    const float* W1 = (const float*)d_in[1];
    const float* g1 = (const float*)d_in[2];
    const float* b1 = (const float*)d_in[3];
    const float* m1 = (const float*)d_in[4];
    const float* v1 = (const float*)d_in[5];
    const float* r  = (const float*)d_in[6];
    const float* im = (const float*)d_in[7];
    const float* rb = (const float*)d_in[8];
    const float* ib = (const float*)d_in[9];
    const float* W2 = (const float*)d_in[10];
    const float* g2 = (const float*)d_in[11];
    const float* b2 = (const float*)d_in[12];
    const float* m2 = (const float*)d_in[13];
    const float* v2 = (const float*)d_in[14];
    float* out = (float*)d_out;

    fc1_kernel<<<dim3(32, 6, 8), 256>>>(x, W1, g1, b1, m1, v1);
    fft_mix_kernel<<<Bb * Hh, 256>>>(r, im, rb, ib);
    fc2_kernel<<<dim3(32, 3, 8), 128>>>(W2, g2, b2, m2, v2, out);
}

// round 10
// speedup vs baseline: 1.8604x; 1.2791x over previous
#include <cuda_runtime.h>
#include <cuda_bf16.h>
#include <math.h>
#include <cstdint>

#define EPSV 1e-5f

constexpr int Bb = 8;
constexpr int NT = 4096;   // tokens (FFT length)
constexpr int Cc = 192;    // input/output channels
constexpr int Hh = 768;    // hidden channels

// scratch: h in [B, H, N] (FFT rows contiguous) and transposed [B, N, H]
__device__ float g_h1[25165824];  // 8*768*4096
__device__ float g_h2[25165824];  // 8*4096*768

// ===================== mma.sync helpers (baseline PTX, sm_80+) =====================
__device__ __forceinline__ void mma16816(float* c, const uint32_t* a, const uint32_t* b) {
    asm volatile(
        "mma.sync.aligned.m16n8k16.row.col.f32.bf16.bf16.f32 "
        "{%0,%1,%2,%3}, {%4,%5,%6,%7}, {%8,%9}, {%0,%1,%2,%3};"
        : "+f"(c[0]), "+f"(c[1]), "+f"(c[2]), "+f"(c[3])
        : "r"(a[0]), "r"(a[1]), "r"(a[2]), "r"(a[3]), "r"(b[0]), "r"(b[1]));
}

union BfPack { __nv_bfloat16 b[2]; uint32_t u; };

// split pair (f0 low, f1 high) into hi/lo bf16 words
__device__ __forceinline__ void split_pair(float f0, float f1, uint32_t& hi, uint32_t& lo) {
    BfPack H, L;
    H.b[0] = __float2bfloat16(f0);
    H.b[1] = __float2bfloat16(f1);
    L.b[0] = __float2bfloat16(f0 - __bfloat162float(H.b[0]));
    L.b[1] = __float2bfloat16(f1 - __bfloat162float(H.b[1]));
    hi = H.u; lo = L.u;
}

// Producer: [rows x 32] fp32 tile (row stride ldf) -> bf16 hi/lo smem tiles,
// K-major, row stride 20 words (16 data words + 4 pad -> conflict-free frags).
__device__ __forceinline__ void produce_tile(
    const float* __restrict__ src, int ldf, int rows,
    uint32_t* __restrict__ H, uint32_t* __restrict__ L, int tid, int nth)
{
    for (int i = tid; i < rows * 2; i += nth) {
        int r = i >> 1, h = i & 1;
        const float* p = src + (size_t)r * ldf + h * 16;
        float4 u0 = *(const float4*)(p + 0);
        float4 u1 = *(const float4*)(p + 4);
        float4 u2 = *(const float4*)(p + 8);
        float4 u3 = *(const float4*)(p + 12);
        uint32_t hw[8], lw[8];
        split_pair(u0.x, u0.y, hw[0], lw[0]);
        split_pair(u0.z, u0.w, hw[1], lw[1]);
        split_pair(u1.x, u1.y, hw[2], lw[2]);
        split_pair(u1.z, u1.w, hw[3], lw[3]);
        split_pair(u2.x, u2.y, hw[4], lw[4]);
        split_pair(u2.z, u2.w, hw[5], lw[5]);
        split_pair(u3.x, u3.y, hw[6], lw[6]);
        split_pair(u3.z, u3.w, hw[7], lw[7]);
        uint32_t* dH = H + r * 20 + h * 8;
        uint32_t* dL = L + r * 20 + h * 8;
        *(uint4*)(dH + 0) = make_uint4(hw[0], hw[1], hw[2], hw[3]);
        *(uint4*)(dH + 4) = make_uint4(hw[4], hw[5], hw[6], hw[7]);
        *(uint4*)(dL + 0) = make_uint4(lw[0], lw[1], lw[2], lw[3]);
        *(uint4*)(dL + 4) = make_uint4(lw[4], lw[5], lw[6], lw[7]);
    }
}

// load A fragment (m16k16) at row base r0, k16 word offset kw
__device__ __forceinline__ void ldfragA(uint32_t* a, const uint32_t* S, int r0, int kw, int g, int tig) {
    a[0] = S[(r0 + g) * 20 + kw + tig];
    a[1] = S[(r0 + g + 8) * 20 + kw + tig];
    a[2] = S[(r0 + g) * 20 + kw + 4 + tig];
    a[3] = S[(r0 + g + 8) * 20 + kw + 4 + tig];
}
// load B fragment (n8k16) at row base n (B stored [n][k])
__device__ __forceinline__ void ldfragB(uint32_t* b, const uint32_t* S, int n0, int kw, int g, int tig) {
    b[0] = S[(n0 + g) * 20 + kw + tig];
    b[1] = S[(n0 + g) * 20 + kw + 4 + tig];
}

// ---------------------------------------------------------------------------
// fc1: h[b,hc,n] = relu(BN(X @ W1^T)). Tile 128 tok x 128 hc, K=192 (6 stages).
// 8 warps: 2(M=64) x 4(N=32). Output staged through smem -> coalesced [B,H,N].
// ---------------------------------------------------------------------------
__global__ __launch_bounds__(256, 2) void fc1_mma(
    const float* __restrict__ X, const float* __restrict__ W1,
    const float* __restrict__ g1, const float* __restrict__ b1,
    const float* __restrict__ m1, const float* __restrict__ v1)
{
    __shared__ uint32_t AH[128 * 20], AL[128 * 20], BH[128 * 20], BL[128 * 20];
    __shared__ float scS[128], biS[128];

    const int tid = threadIdx.x, wid = tid >> 5, lane = tid & 31;
    const int g = lane >> 2, tig = lane & 3;
    const int t0 = blockIdx.x * 128;    // global token base (flat 32768)
    const int n0 = blockIdx.y * 128;    // hc base
    const int wm0 = (wid >> 2) * 64;
    const int wn0 = (wid & 3) * 32;

    if (tid < 128) {
        int hc = n0 + tid;
        float s = g1[hc] * rsqrtf(v1[hc] + EPSV);
        scS[tid] = s;
        biS[tid] = b1[hc] - m1[hc] * s;
    }

    float acc[4][4][4];
#pragma unroll
    for (int mi = 0; mi < 4; mi++)
#pragma unroll
        for (int ni = 0; ni < 4; ni++)
#pragma unroll
            for (int q = 0; q < 4; q++) acc[mi][ni][q] = 0.f;

    for (int s = 0; s < 6; s++) {
        int k0 = s * 32;
        produce_tile(X + (size_t)t0 * Cc + k0, Cc, 128, AH, AL, tid, 256);
        produce_tile(W1 + (size_t)n0 * Cc + k0, Cc, 128, BH, BL, tid, 256);
        __syncthreads();
#pragma unroll
        for (int k16 = 0; k16 < 2; k16++) {
            int kw = k16 * 8;
            const uint32_t* APs[3] = {AH, AL, AH};
            const uint32_t* BPs[3] = {BH, BH, BL};
#pragma unroll
            for (int sp = 0; sp < 3; sp++) {
                uint32_t a[4][4], b[4][2];
#pragma unroll
                for (int mi = 0; mi < 4; mi++)
                    ldfragA(a[mi], APs[sp], wm0 + mi * 16, kw, g, tig);
#pragma unroll
                for (int ni = 0; ni < 4; ni++)
                    ldfragB(b[ni], BPs[sp], wn0 + ni * 8, kw, g, tig);
#pragma unroll
                for (int mi = 0; mi < 4; mi++)
#pragma unroll
                    for (int ni = 0; ni < 4; ni++)
                        mma16816(acc[mi][ni], a[mi], b[ni]);
            }
        }
        __syncthreads();
    }

    // epilogue: BN+relu, stage [n][m] halves through smem, coalesced store
    const int b = t0 >> 12;
    const int tn0 = t0 & 4095;
    float* Cst = (float*)AH;      // 64 x 132 floats = 33792 B (fits in 40960)
    const int myh = (wid & 3) >> 1;
    for (int h = 0; h < 2; h++) {
        if (myh == h) {
#pragma unroll
            for (int mi = 0; mi < 4; mi++)
#pragma unroll
                for (int ni = 0; ni < 4; ni++) {
                    int m = wm0 + mi * 16 + g;
                    int nn = wn0 + ni * 8 + tig * 2;        // 0..127 local
                    int nl = nn - h * 64;
                    float s0 = scS[nn], s1 = scS[nn + 1];
                    float c0 = biS[nn], c1 = biS[nn + 1];
                    Cst[nl * 132 + m]            = fmaxf(fmaf(acc[mi][ni][0], s0, c0), 0.f);
                    Cst[(nl + 1) * 132 + m]      = fmaxf(fmaf(acc[mi][ni][1], s1, c1), 0.f);
                    Cst[nl * 132 + m + 8]        = fmaxf(fmaf(acc[mi][ni][2], s0, c0), 0.f);
                    Cst[(nl + 1) * 132 + m + 8]  = fmaxf(fmaf(acc[mi][ni][3], s1, c1), 0.f);
                }
        }
        __syncthreads();
        {
            int n = tid >> 2, mseg = (tid & 3) * 32;
            float* dst = g_h1 + (size_t)(b * Hh + n0 + h * 64 + n) * NT + tn0 + mseg;
            const float* srcr = &Cst[n * 132 + mseg];
#pragma unroll
            for (int q = 0; q < 32; q += 4)
                *(float4*)(dst + q) = *(const float4*)(srcr + q);
        }
        __syncthreads();
    }
}

// ---------------------------------------------------------------------------
// FFT(4096) -> per-channel complex mix+relu -> IFFT(4096), in place on g_h1.
// Fused radix-16 passes; no digit-reversal needed (mix is bin-order-invariant).
// ---------------------------------------------------------------------------
__device__ __forceinline__ float2 cmulf(float2 a, float2 b) {
    return make_float2(a.x * b.x - a.y * b.y, a.x * b.y + a.y * b.x);
}
__device__ __forceinline__ float2 cadd(float2 a, float2 b) { return make_float2(a.x + b.x, a.y + b.y); }
__device__ __forceinline__ float2 csub(float2 a, float2 b) { return make_float2(a.x - b.x, a.y - b.y); }

#define SWZ(i) ((i) ^ (((i) >> 4) & 15))

__device__ __forceinline__ float2 twid(const float2* __restrict__ T, int m) {
    float2 w = T[m & 1023];
    int q = m >> 10;
    if (q == 1) return make_float2(w.y, -w.x);
    if (q == 2) return make_float2(-w.x, -w.y);
    return w;
}
__device__ __forceinline__ float2 twidc(const float2* __restrict__ T, int m) {
    float2 w = twid(T, m);
    return make_float2(w.x, -w.y);
}

__global__ __launch_bounds__(256) void fft_mix_kernel(
    const float* __restrict__ R, const float* __restrict__ Im,
    const float* __restrict__ RB, const float* __restrict__ IB)
{
    __shared__ float2 S[4096];
    __shared__ float2 T[1024];

    const int tid = threadIdx.x;
    const int row = blockIdx.x;
    const int hc = row % Hh;
    float* data = g_h1 + (size_t)row * NT;

    for (int m = tid; m < 1024; m += 256) {
        float s, c;
        sincospif(-(float)m / 2048.0f, &s, &c);
        T[m] = make_float2(c, s);
    }
    for (int t = tid; t < 4096; t += 256)
        S[SWZ(t)] = make_float2(data[t], 0.f);
    __syncthreads();

#pragma unroll
    for (int ls = 12; ls >= 4; ls -= 4) {
        const int Q  = 1 << (ls - 2);
        const int Q4 = 1 << (ls - 4);
        const int stepw  = 1 << (12 - ls);
        const int stepw4 = stepw << 2;
        const int j = tid & (Q4 - 1);
        const int base = (tid >> (ls - 4)) << ls;

        float2 X[4][4];
#pragma unroll
        for (int q = 0; q < 4; q++)
#pragma unroll
            for (int p = 0; p < 4; p++)
                X[q][p] = S[SWZ(base + j + p * Q4 + q * Q)];

#pragma unroll
        for (int p = 0; p < 4; p++) {
            float2 a = X[0][p], b = X[1][p], c = X[2][p], d = X[3][p];
            float2 apc = cadd(a, c), amc = csub(a, c);
            float2 bpd = cadd(b, d), bmd = csub(b, d);
            int e = (j + p * Q4) * stepw;
            X[0][p] = cadd(apc, bpd);
            X[1][p] = cmulf(twid(T, e),     make_float2(amc.x + bmd.y, amc.y - bmd.x));
            X[2][p] = cmulf(twid(T, 2 * e), csub(apc, bpd));
            X[3][p] = cmulf(twid(T, 3 * e), make_float2(amc.x - bmd.y, amc.y + bmd.x));
        }
        {
            int e2 = j * stepw4;
            float2 w1 = twid(T, e2), w2 = twid(T, 2 * e2), w3 = twid(T, 3 * e2);
#pragma unroll
            for (int q = 0; q < 4; q++) {
                float2 a = X[q][0], b = X[q][1], c = X[q][2], d = X[q][3];
                float2 apc = cadd(a, c), amc = csub(a, c);
                float2 bpd = cadd(b, d), bmd = csub(b, d);
                X[q][0] = cadd(apc, bpd);
                X[q][1] = cmulf(w1, make_float2(amc.x + bmd.y, amc.y - bmd.x));
                X[q][2] = cmulf(w2, csub(apc, bpd));
                X[q][3] = cmulf(w3, make_float2(amc.x - bmd.y, amc.y + bmd.x));
            }
        }
        __syncthreads();
#pragma unroll
        for (int q = 0; q < 4; q++)
#pragma unroll
            for (int p = 0; p < 4; p++)
                S[SWZ(base + j + p * Q4 + q * Q)] = X[q][p];
        __syncthreads();
    }

    const float rd  = R[hc * (Hh + 1)];
    const float idg = Im[hc * (Hh + 1)];
    const float rbv = RB[hc], ibv = IB[hc];
    const float inv = 0.015625f;
    for (int t = tid; t < 4096; t += 256) {
        float2 v = S[SWZ(t)];
        float re = v.x * inv, im2 = v.y * inv;
        float xr = fmaxf(fmaf(rd, re, fmaf(-idg, im2, rbv)), 0.f);
        float xi = fmaxf(fmaf(rd, im2, fmaf(idg, re, ibv)), 0.f);
        S[SWZ(t)] = make_float2(xr, xi);
    }
    __syncthreads();

#pragma unroll
    for (int ls = 4; ls <= 12; ls += 4) {
        const int Q  = 1 << (ls - 2);
        const int Q4 = 1 << (ls - 4);
        const int stepw  = 1 << (12 - ls);
        const int stepw4 = stepw << 2;
        const int j = tid & (Q4 - 1);
        const int base = (tid >> (ls - 4)) << ls;

        float2 X[4][4];
#pragma unroll
        for (int q = 0; q < 4; q++)
#pragma unroll
            for (int p = 0; p < 4; p++)
                X[q][p] = S[SWZ(base + j + p * Q4 + q * Q)];

        {
            int e2 = j * stepw4;
            float2 w1 = twidc(T, e2), w2 = twidc(T, 2 * e2), w3 = twidc(T, 3 * e2);
#pragma unroll
            for (int q = 0; q < 4; q++) {
                float2 a = X[q][0];
                float2 b = cmulf(w1, X[q][1]);
                float2 c = cmulf(w2, X[q][2]);
                float2 d = cmulf(w3, X[q][3]);
                float2 apc = cadd(a, c), amc = csub(a, c);
                float2 bpd = cadd(b, d), bmd = csub(b, d);
                X[q][0] = cadd(apc, bpd);
                X[q][1] = make_float2(amc.x - bmd.y, amc.y + bmd.x);
                X[q][2] = csub(apc, bpd);
                X[q][3] = make_float2(amc.x + bmd.y, amc.y - bmd.x);
            }
        }
#pragma unroll
        for (int p = 0; p < 4; p++) {
            int e = (j + p * Q4) * stepw;
            float2 a = X[0][p];
            float2 b = cmulf(twidc(T, e),     X[1][p]);
            float2 c = cmulf(twidc(T, 2 * e), X[2][p]);
            float2 d = cmulf(twidc(T, 3 * e), X[3][p]);
            float2 apc = cadd(a, c), amc = csub(a, c);
            float2 bpd = cadd(b, d), bmd = csub(b, d);
            X[0][p] = cadd(apc, bpd);
            X[1][p] = make_float2(amc.x - bmd.y, amc.y + bmd.x);
            X[2][p] = csub(apc, bpd);
            X[3][p] = make_float2(amc.x + bmd.y, amc.y - bmd.x);
        }
        __syncthreads();
#pragma unroll
        for (int q = 0; q < 4; q++)
#pragma unroll
            for (int p = 0; p < 4; p++)
                S[SWZ(base + j + p * Q4 + q * Q)] = X[q][p];
        __syncthreads();
    }

    for (int t = tid; t < 4096; t += 256)
        data[t] = S[SWZ(t)].x * inv;
}

// ---------------------------------------------------------------------------
// transpose: g_h1 [B,H,N] -> g_h2 [B,N,H]  (coalesced both sides)
// ---------------------------------------------------------------------------
__global__ __launch_bounds__(256) void transpose_kernel()
{
    __shared__ float t[32][33];
    const int b = blockIdx.z;
    const int n0 = blockIdx.x * 32, h0 = blockIdx.y * 32;
    const float* src = g_h1 + (size_t)b * Hh * NT;
    float* dst = g_h2 + (size_t)b * NT * Hh;
    const int tx = threadIdx.x, ty = threadIdx.y;
#pragma unroll
    for (int j = 0; j < 32; j += 8)
        t[ty + j][tx] = src[(size_t)(h0 + ty + j) * NT + n0 + tx];
    __syncthreads();
#pragma unroll
    for (int j = 0; j < 32; j += 8)
        dst[(size_t)(n0 + ty + j) * Hh + h0 + tx] = t[tx][ty + j];
}

// ---------------------------------------------------------------------------
// fc2: y[b,n,c] = BN(h_t @ W2^T). Tile 64 tok x 192 c, K=768 (24 stages).
// 8 warps: 2(M=32) x 4(N=48). Direct fragment store (m-major output).
// ---------------------------------------------------------------------------
__global__ __launch_bounds__(256, 2) void fc2_mma(
    const float* __restrict__ W2,
    const float* __restrict__ g2, const float* __restrict__ b2,
    const float* __restrict__ m2, const float* __restrict__ v2,
    float* __restrict__ Y)
{
    __shared__ uint32_t AH[64 * 20], AL[64 * 20], BH[192 * 20], BL[192 * 20];
    __shared__ float scS[192], biS[192];

    const int tid = threadIdx.x, wid = tid >> 5, lane = tid & 31;
    const int g = lane >> 2, tig = lane & 3;
    const int t0 = blockIdx.x * 64;     // global token base (flat 32768)
    const int wm0 = (wid >> 2) * 32;
    const int wn0 = (wid & 3) * 48;

    if (tid < 192) {
        float s = g2[tid] * rsqrtf(v2[tid] + EPSV);
        scS[tid] = s;
        biS[tid] = b2[tid] - m2[tid] * s;
    }

    float acc[2][6][4];
#pragma unroll
    for (int mi = 0; mi < 2; mi++)
#pragma unroll
        for (int ni = 0; ni < 6; ni++)
#pragma unroll
            for (int q = 0; q < 4; q++) acc[mi][ni][q] = 0.f;

    for (int s = 0; s < 24; s++) {
        int k0 = s * 32;
        produce_tile(g_h2 + (size_t)t0 * Hh + k0, Hh, 64, AH, AL, tid, 256);
        produce_tile(W2 + k0, Hh, 192, BH, BL, tid, 256);
        __syncthreads();
#pragma unroll
        for (int k16 = 0; k16 < 2; k16++) {
            int kw = k16 * 8;
            const uint32_t* APs[3] = {AH, AL, AH};
            const uint32_t* BPs[3] = {BH, BH, BL};
#pragma unroll
            for (int sp = 0; sp < 3; sp++) {
                uint32_t a[2][4], b[6][2];
#pragma unroll
                for (int mi = 0; mi < 2; mi++)
                    ldfragA(a[mi], APs[sp], wm0 + mi * 16, kw, g, tig);
#pragma unroll
                for (int ni = 0; ni < 6; ni++)
                    ldfragB(b[ni], BPs[sp], wn0 + ni * 8, kw, g, tig);
#pragma unroll
                for (int mi = 0; mi < 2; mi++)
#pragma unroll
                    for (int ni = 0; ni < 6; ni++)
                        mma16816(acc[mi][ni], a[mi], b[ni]);
            }
        }
        __syncthreads();
    }

    // epilogue: BN + direct store (Y is token-major, channel pairs contiguous)
#pragma unroll
    for (int mi = 0; mi < 2; mi++)
#pragma unroll
        for (int ni = 0; ni < 6; ni++) {
            int m = wm0 + mi * 16 + g;
            int nn = wn0 + ni * 8 + tig * 2;
            float s0 = scS[nn], s1 = scS[nn + 1];
            float c0 = biS[nn], c1 = biS[nn + 1];
            float2 v0 = make_float2(fmaf(acc[mi][ni][0], s0, c0), fmaf(acc[mi][ni][1], s1, c1));
            float2 v1 = make_float2(fmaf(acc[mi][ni][2], s0, c0), fmaf(acc[mi][ni][3], s1, c1));
            *(float2*)(Y + (size_t)(t0 + m) * Cc + nn) = v0;
            *(float2*)(Y + (size_t)(t0 + m + 8) * Cc + nn) = v1;
        }
}

// ---------------------------------------------------------------------------
extern "C" void kernel_launch(void* const* d_in, const int* in_sizes, int n_in,
                              void* d_out, int out_size) {
    const float* x  = (const float*)d_in[0];
    const float* W1 = (const float*)d_in[1];
    const float* g1 = (const float*)d_in[2];
    const float* b1 = (const float*)d_in[3];
    const float* m1 = (const float*)d_in[4];
    const float* v1 = (const float*)d_in[5];
    const float* r  = (const float*)d_in[6];
    const float* im = (const float*)d_in[7];
    const float* rb = (const float*)d_in[8];
    const float* ib = (const float*)d_in[9];
    const float* W2 = (const float*)d_in[10];
    const float* g2 = (const float*)d_in[11];
    const float* b2 = (const float*)d_in[12];
    const float* m2 = (const float*)d_in[13];
    const float* v2 = (const float*)d_in[14];
    float* out = (float*)d_out;

    fc1_mma<<<dim3(256, 6), 256>>>(x, W1, g1, b1, m1, v1);
    fft_mix_kernel<<<Bb * Hh, 256>>>(r, im, rb, ib);
    transpose_kernel<<<dim3(128, 24, 8), dim3(32, 8)>>>();
    fc2_mma<<<512, 256>>>(W2, g2, b2, m2, v2, out);
}

// round 14
// speedup vs baseline: 2.0310x; 1.0917x over previous
#include <cuda_runtime.h>
#include <cuda_bf16.h>
#include <math.h>
#include <cstdint>

#define EPSV 1e-5f

constexpr int Bb = 8;
constexpr int NT = 4096;   // tokens (FFT length)
constexpr int Cc = 192;    // input/output channels
constexpr int Hh = 768;    // hidden channels

// fp32 scratch (FFT works in place here)
__device__ float g_h1[25165824];            // [B, H, N]
// bf16 hi/lo operand buffers
__device__ __nv_bfloat16 g_xh[6291456],  g_xl[6291456];    // x  [B*N, C]
__device__ __nv_bfloat16 g_w1h[147456],  g_w1l[147456];    // W1 [H, C]
__device__ __nv_bfloat16 g_w2h[147456],  g_w2l[147456];    // W2 [C, H]
__device__ __nv_bfloat16 g_h2h[25165824], g_h2l[25165824]; // h  [B, N, H] transposed

// ===================== helpers =====================
__device__ __forceinline__ uint32_t smem_u32(const void* p) {
    uint32_t a;
    asm("{ .reg .u64 t; cvta.to.shared.u64 t, %1; cvt.u32.u64 %0, t; }" : "=r"(a) : "l"(p));
    return a;
}
__device__ __forceinline__ void cpasync16(uint32_t dst, const void* src) {
    asm volatile("cp.async.cg.shared.global [%0], [%1], 16;" :: "r"(dst), "l"(src));
}
#define CP_COMMIT() asm volatile("cp.async.commit_group;" ::: "memory")
#define CP_WAIT1() asm volatile("cp.async.wait_group 1;" ::: "memory")
#define CP_WAIT0() asm volatile("cp.async.wait_group 0;" ::: "memory")

__device__ __forceinline__ void mma16816(float* c, const uint32_t* a, const uint32_t* b) {
    asm volatile(
        "mma.sync.aligned.m16n8k16.row.col.f32.bf16.bf16.f32 "
        "{%0,%1,%2,%3}, {%4,%5,%6,%7}, {%8,%9}, {%0,%1,%2,%3};"
        : "+f"(c[0]), "+f"(c[1]), "+f"(c[2]), "+f"(c[3])
        : "r"(a[0]), "r"(a[1]), "r"(a[2]), "r"(a[3]), "r"(b[0]), "r"(b[1]));
}

union BfPack { __nv_bfloat16 b[2]; uint32_t u; };
__device__ __forceinline__ void split_pair(float f0, float f1, uint32_t& hi, uint32_t& lo) {
    BfPack H, L;
    H.b[0] = __float2bfloat16(f0);
    H.b[1] = __float2bfloat16(f1);
    L.b[0] = __float2bfloat16(f0 - __bfloat162float(H.b[0]));
    L.b[1] = __float2bfloat16(f1 - __bfloat162float(H.b[1]));
    hi = H.u; lo = L.u;
}

// fragment loads from padded K-major bf16 tiles (row stride 20 words)
__device__ __forceinline__ void ldfragA(uint32_t* a, const uint32_t* S, int r0, int kw, int g, int tig) {
    a[0] = S[(r0 + g) * 20 + kw + tig];
    a[1] = S[(r0 + g + 8) * 20 + kw + tig];
    a[2] = S[(r0 + g) * 20 + kw + 4 + tig];
    a[3] = S[(r0 + g + 8) * 20 + kw + 4 + tig];
}
__device__ __forceinline__ void ldfragB(uint32_t* b, const uint32_t* S, int n0, int kw, int g, int tig) {
    b[0] = S[(n0 + g) * 20 + kw + tig];
    b[1] = S[(n0 + g) * 20 + kw + 4 + tig];
}

// ---------------------------------------------------------------------------
// prepass: split fp32 -> bf16 hi/lo (vectorized, grid-stride)
// ---------------------------------------------------------------------------
__global__ __launch_bounds__(256) void conv_pair(
    const float* __restrict__ s, __nv_bfloat16* __restrict__ h,
    __nv_bfloat16* __restrict__ l, int n4)
{
    for (int i = blockIdx.x * blockDim.x + threadIdx.x; i < n4; i += gridDim.x * blockDim.x) {
        float4 v = ((const float4*)s)[i];
        uint32_t h0, h1, l0, l1;
        split_pair(v.x, v.y, h0, l0);
        split_pair(v.z, v.w, h1, l1);
        ((uint2*)h)[i] = make_uint2(h0, h1);
        ((uint2*)l)[i] = make_uint2(l0, l1);
    }
}

// ---------------------------------------------------------------------------
// fc1: h[b,hc,n] = relu(BN(X @ W1^T)). Tile 128 tok x 128 hc, K=192.
// cp.async double-buffered bf16 stages; 8 warps 2(M=64) x 4(N=32).
// dynamic smem: 2 x 40960 B stage buffers.
// ---------------------------------------------------------------------------
__global__ __launch_bounds__(256, 2) void fc1_mma(
    const float* __restrict__ g1, const float* __restrict__ b1,
    const float* __restrict__ m1, const float* __restrict__ v1)
{
    extern __shared__ char dynsmem[];
    const uint32_t sbase = smem_u32(dynsmem);
    __shared__ float scS[128], biS[128];

    const int tid = threadIdx.x, wid = tid >> 5, lane = tid & 31;
    const int g = lane >> 2, tig = lane & 3;
    const int t0 = blockIdx.x * 128;    // token base (flat 32768)
    const int n0 = blockIdx.y * 128;    // hc base
    const int wm0 = (wid >> 2) * 64;
    const int wn0 = (wid & 3) * 32;

    if (tid < 128) {
        int hc = n0 + tid;
        float s = g1[hc] * rsqrtf(v1[hc] + EPSV);
        scS[tid] = s;
        biS[tid] = b1[hc] - m1[hc] * s;
    }

    float acc[4][4][4];
#pragma unroll
    for (int mi = 0; mi < 4; mi++)
#pragma unroll
        for (int ni = 0; ni < 4; ni++)
#pragma unroll
            for (int q = 0; q < 4; q++) acc[mi][ni][q] = 0.f;

    const int r = tid >> 2, c = tid & 3;          // 128 rows x 4 chunks: exactly 512/... (2 iters)
    // stage issue: 128 rows x 4 chunks for each of AH/AL/BH/BL
    auto issue = [&](int s, int bi) {
        uint32_t sb = sbase + bi * 40960;
        int k0 = s * 32;
#pragma unroll
        for (int it = 0; it < 2; it++) {
            int rr = r + it * 64;
            uint32_t woff = (rr * 20 + c * 4) * 4;
            const __nv_bfloat16* ax = g_xh + (size_t)(t0 + rr) * Cc + k0 + c * 8;
            cpasync16(sb + woff,         ax);
            cpasync16(sb + 10240 + woff, g_xl + (size_t)(t0 + rr) * Cc + k0 + c * 8);
            cpasync16(sb + 20480 + woff, g_w1h + (size_t)(n0 + rr) * Cc + k0 + c * 8);
            cpasync16(sb + 30720 + woff, g_w1l + (size_t)(n0 + rr) * Cc + k0 + c * 8);
        }
        CP_COMMIT();
    };

    issue(0, 0);
    for (int s = 0; s < 6; s++) {
        if (s + 1 < 6) { issue(s + 1, (s + 1) & 1); CP_WAIT1(); }
        else CP_WAIT0();
        __syncthreads();
        const uint32_t* AH = (const uint32_t*)(dynsmem + (s & 1) * 40960);
        const uint32_t* AL = AH + 2560;
        const uint32_t* BH = AH + 5120;
        const uint32_t* BL = AH + 7680;
#pragma unroll
        for (int k16 = 0; k16 < 2; k16++) {
            int kw = k16 * 8;
            const uint32_t* APs[3] = {AH, AL, AH};
            const uint32_t* BPs[3] = {BH, BH, BL};
#pragma unroll
            for (int sp = 0; sp < 3; sp++) {
                uint32_t a[4][4], b[4][2];
#pragma unroll
                for (int mi = 0; mi < 4; mi++)
                    ldfragA(a[mi], APs[sp], wm0 + mi * 16, kw, g, tig);
#pragma unroll
                for (int ni = 0; ni < 4; ni++)
                    ldfragB(b[ni], BPs[sp], wn0 + ni * 8, kw, g, tig);
#pragma unroll
                for (int mi = 0; mi < 4; mi++)
#pragma unroll
                    for (int ni = 0; ni < 4; ni++)
                        mma16816(acc[mi][ni], a[mi], b[ni]);
            }
        }
        __syncthreads();
    }

    // epilogue: BN+relu, stage [n][m] halves through smem, coalesced [B,H,N] store
    const int b = t0 >> 12;
    const int tn0 = t0 & 4095;
    float* Cst = (float*)dynsmem;       // 64 x 132 floats = 33792 B
    const int myh = (wid & 3) >> 1;
    for (int h = 0; h < 2; h++) {
        if (myh == h) {
#pragma unroll
            for (int mi = 0; mi < 4; mi++)
#pragma unroll
                for (int ni = 0; ni < 4; ni++) {
                    int m = wm0 + mi * 16 + g;
                    int nn = wn0 + ni * 8 + tig * 2;
                    int nl = nn - h * 64;
                    float s0 = scS[nn], s1 = scS[nn + 1];
                    float c0 = biS[nn], c1 = biS[nn + 1];
                    Cst[nl * 132 + m]            = fmaxf(fmaf(acc[mi][ni][0], s0, c0), 0.f);
                    Cst[(nl + 1) * 132 + m]      = fmaxf(fmaf(acc[mi][ni][1], s1, c1), 0.f);
                    Cst[nl * 132 + m + 8]        = fmaxf(fmaf(acc[mi][ni][2], s0, c0), 0.f);
                    Cst[(nl + 1) * 132 + m + 8]  = fmaxf(fmaf(acc[mi][ni][3], s1, c1), 0.f);
                }
        }
        __syncthreads();
        {
            int n = tid >> 2, mseg = (tid & 3) * 32;
            float* dst = g_h1 + (size_t)(b * Hh + n0 + h * 64 + n) * NT + tn0 + mseg;
            const float* srcr = &Cst[n * 132 + mseg];
#pragma unroll
            for (int q = 0; q < 32; q += 4)
                *(float4*)(dst + q) = *(const float4*)(srcr + q);
        }
        __syncthreads();
    }
}

// ---------------------------------------------------------------------------
// FFT(4096) -> per-channel complex mix+relu -> IFFT(4096), in place on g_h1.
// Fused radix-16 passes; no digit-reversal needed (mix is bin-order-invariant).
// ---------------------------------------------------------------------------
__device__ __forceinline__ float2 cmulf(float2 a, float2 b) {
    return make_float2(a.x * b.x - a.y * b.y, a.x * b.y + a.y * b.x);
}
__device__ __forceinline__ float2 cadd(float2 a, float2 b) { return make_float2(a.x + b.x, a.y + b.y); }
__device__ __forceinline__ float2 csub(float2 a, float2 b) { return make_float2(a.x - b.x, a.y - b.y); }

#define SWZ(i) ((i) ^ (((i) >> 4) & 15))

__device__ __forceinline__ float2 twid(const float2* __restrict__ T, int m) {
    float2 w = T[m & 1023];
    int q = m >> 10;
    if (q == 1) return make_float2(w.y, -w.x);
    if (q == 2) return make_float2(-w.x, -w.y);
    return w;
}
__device__ __forceinline__ float2 twidc(const float2* __restrict__ T, int m) {
    float2 w = twid(T, m);
    return make_float2(w.x, -w.y);
}

__global__ __launch_bounds__(256) void fft_mix_kernel(
    const float* __restrict__ R, const float* __restrict__ Im,
    const float* __restrict__ RB, const float* __restrict__ IB)
{
    __shared__ float2 S[4096];
    __shared__ float2 T[1024];

    const int tid = threadIdx.x;
    const int row = blockIdx.x;
    const int hc = row % Hh;
    float* data = g_h1 + (size_t)row * NT;

    for (int m = tid; m < 1024; m += 256) {
        float s, c;
        sincospif(-(float)m / 2048.0f, &s, &c);
        T[m] = make_float2(c, s);
    }
    for (int t = tid; t < 4096; t += 256)
        S[SWZ(t)] = make_float2(data[t], 0.f);
    __syncthreads();

#pragma unroll
    for (int ls = 12; ls >= 4; ls -= 4) {
        const int Q  = 1 << (ls - 2);
        const int Q4 = 1 << (ls - 4);
        const int stepw  = 1 << (12 - ls);
        const int stepw4 = stepw << 2;
        const int j = tid & (Q4 - 1);
        const int base = (tid >> (ls - 4)) << ls;

        float2 X[4][4];
#pragma unroll
        for (int q = 0; q < 4; q++)
#pragma unroll
            for (int p = 0; p < 4; p++)
                X[q][p] = S[SWZ(base + j + p * Q4 + q * Q)];

#pragma unroll
        for (int p = 0; p < 4; p++) {
            float2 a = X[0][p], b = X[1][p], c = X[2][p], d = X[3][p];
            float2 apc = cadd(a, c), amc = csub(a, c);
            float2 bpd = cadd(b, d), bmd = csub(b, d);
            int e = (j + p * Q4) * stepw;
            X[0][p] = cadd(apc, bpd);
            X[1][p] = cmulf(twid(T, e),     make_float2(amc.x + bmd.y, amc.y - bmd.x));
            X[2][p] = cmulf(twid(T, 2 * e), csub(apc, bpd));
            X[3][p] = cmulf(twid(T, 3 * e), make_float2(amc.x - bmd.y, amc.y + bmd.x));
        }
        {
            int e2 = j * stepw4;
            float2 w1 = twid(T, e2), w2 = twid(T, 2 * e2), w3 = twid(T, 3 * e2);
#pragma unroll
            for (int q = 0; q < 4; q++) {
                float2 a = X[q][0], b = X[q][1], c = X[q][2], d = X[q][3];
                float2 apc = cadd(a, c), amc = csub(a, c);
                float2 bpd = cadd(b, d), bmd = csub(b, d);
                X[q][0] = cadd(apc, bpd);
                X[q][1] = cmulf(w1, make_float2(amc.x + bmd.y, amc.y - bmd.x));
                X[q][2] = cmulf(w2, csub(apc, bpd));
                X[q][3] = cmulf(w3, make_float2(amc.x - bmd.y, amc.y + bmd.x));
            }
        }
        __syncthreads();
#pragma unroll
        for (int q = 0; q < 4; q++)
#pragma unroll
            for (int p = 0; p < 4; p++)
                S[SWZ(base + j + p * Q4 + q * Q)] = X[q][p];
        __syncthreads();
    }

    const float rd  = R[hc * (Hh + 1)];
    const float idg = Im[hc * (Hh + 1)];
    const float rbv = RB[hc], ibv = IB[hc];
    const float inv = 0.015625f;
    for (int t = tid; t < 4096; t += 256) {
        float2 v = S[SWZ(t)];
        float re = v.x * inv, im2 = v.y * inv;
        float xr = fmaxf(fmaf(rd, re, fmaf(-idg, im2, rbv)), 0.f);
        float xi = fmaxf(fmaf(rd, im2, fmaf(idg, re, ibv)), 0.f);
        S[SWZ(t)] = make_float2(xr, xi);
    }
    __syncthreads();

#pragma unroll
    for (int ls = 4; ls <= 12; ls += 4) {
        const int Q  = 1 << (ls - 2);
        const int Q4 = 1 << (ls - 4);
        const int stepw  = 1 << (12 - ls);
        const int stepw4 = stepw << 2;
        const int j = tid & (Q4 - 1);
        const int base = (tid >> (ls - 4)) << ls;

        float2 X[4][4];
#pragma unroll
        for (int q = 0; q < 4; q++)
#pragma unroll
            for (int p = 0; p < 4; p++)
                X[q][p] = S[SWZ(base + j + p * Q4 + q * Q)];

        {
            int e2 = j * stepw4;
            float2 w1 = twidc(T, e2), w2 = twidc(T, 2 * e2), w3 = twidc(T, 3 * e2);
#pragma unroll
            for (int q = 0; q < 4; q++) {
                float2 a = X[q][0];
                float2 b = cmulf(w1, X[q][1]);
                float2 c = cmulf(w2, X[q][2]);
                float2 d = cmulf(w3, X[q][3]);
                float2 apc = cadd(a, c), amc = csub(a, c);
                float2 bpd = cadd(b, d), bmd = csub(b, d);
                X[q][0] = cadd(apc, bpd);
                X[q][1] = make_float2(amc.x - bmd.y, amc.y + bmd.x);
                X[q][2] = csub(apc, bpd);
                X[q][3] = make_float2(amc.x + bmd.y, amc.y - bmd.x);
            }
        }
#pragma unroll
        for (int p = 0; p < 4; p++) {
            int e = (j + p * Q4) * stepw;
            float2 a = X[0][p];
            float2 b = cmulf(twidc(T, e),     X[1][p]);
            float2 c = cmulf(twidc(T, 2 * e), X[2][p]);
            float2 d = cmulf(twidc(T, 3 * e), X[3][p]);
            float2 apc = cadd(a, c), amc = csub(a, c);
            float2 bpd = cadd(b, d), bmd = csub(b, d);
            X[0][p] = cadd(apc, bpd);
            X[1][p] = make_float2(amc.x - bmd.y, amc.y + bmd.x);
            X[2][p] = csub(apc, bpd);
            X[3][p] = make_float2(amc.x + bmd.y, amc.y - bmd.x);
        }
        __syncthreads();
#pragma unroll
        for (int q = 0; q < 4; q++)
#pragma unroll
            for (int p = 0; p < 4; p++)
                S[SWZ(base + j + p * Q4 + q * Q)] = X[q][p];
        __syncthreads();
    }

    for (int t = tid; t < 4096; t += 256)
        data[t] = S[SWZ(t)].x * inv;
}

// ---------------------------------------------------------------------------
// transpose+split: g_h1 [B,H,N] fp32 -> g_h2h/g_h2l [B,N,H] bf16
// ---------------------------------------------------------------------------
__global__ __launch_bounds__(256) void transpose_split()
{
    __shared__ float t[32][33];
    const int b = blockIdx.z;
    const int n0 = blockIdx.x * 32, h0 = blockIdx.y * 32;
    const float* src = g_h1 + (size_t)b * Hh * NT;
    const size_t dbase = (size_t)b * NT * Hh;
    const int tx = threadIdx.x, ty = threadIdx.y;
#pragma unroll
    for (int j = 0; j < 32; j += 8)
        t[ty + j][tx] = src[(size_t)(h0 + ty + j) * NT + n0 + tx];
    __syncthreads();
#pragma unroll
    for (int j = 0; j < 32; j += 8) {
        float v = t[tx][ty + j];
        __nv_bfloat16 hi = __float2bfloat16(v);
        __nv_bfloat16 lo = __float2bfloat16(v - __bfloat162float(hi));
        size_t idx = dbase + (size_t)(n0 + ty + j) * Hh + h0 + tx;
        g_h2h[idx] = hi;
        g_h2l[idx] = lo;
    }
}

// ---------------------------------------------------------------------------
// fc2: y[b,n,c] = BN(h_t @ W2^T). Tile 64 tok x 192 c, K=768 (24 stages).
// cp.async double-buffered; 8 warps 2(M=32) x 4(N=48).
// dynamic smem: 2 x 40960 B (A: 2x5120, B: 2x15360).
// ---------------------------------------------------------------------------
__global__ __launch_bounds__(256, 2) void fc2_mma(
    const float* __restrict__ g2, const float* __restrict__ b2,
    const float* __restrict__ m2, const float* __restrict__ v2,
    float* __restrict__ Y)
{
    extern __shared__ char dynsmem[];
    const uint32_t sbase = smem_u32(dynsmem);
    __shared__ float scS[192], biS[192];

    const int tid = threadIdx.x, wid = tid >> 5, lane = tid & 31;
    const int g = lane >> 2, tig = lane & 3;
    const int t0 = blockIdx.x * 64;
    const int wm0 = (wid >> 2) * 32;
    const int wn0 = (wid & 3) * 48;

    if (tid < 192) {
        float s = g2[tid] * rsqrtf(v2[tid] + EPSV);
        scS[tid] = s;
        biS[tid] = b2[tid] - m2[tid] * s;
    }

    float acc[2][6][4];
#pragma unroll
    for (int mi = 0; mi < 2; mi++)
#pragma unroll
        for (int ni = 0; ni < 6; ni++)
#pragma unroll
            for (int q = 0; q < 4; q++) acc[mi][ni][q] = 0.f;

    const int ra = tid >> 2, ca = tid & 3;
    auto issue = [&](int s, int bi) {
        uint32_t sb = sbase + bi * 40960;
        int k0 = s * 32;
        // A: 64 rows x 4 chunks (1 per thread)
        {
            uint32_t woff = (ra * 20 + ca * 4) * 4;
            cpasync16(sb + woff,        g_h2h + (size_t)(t0 + ra) * Hh + k0 + ca * 8);
            cpasync16(sb + 5120 + woff, g_h2l + (size_t)(t0 + ra) * Hh + k0 + ca * 8);
        }
        // B: 192 rows x 4 chunks (3 per thread)
#pragma unroll
        for (int it = 0; it < 3; it++) {
            int rr = ra + it * 64;
            uint32_t woff = (rr * 20 + ca * 4) * 4;
            cpasync16(sb + 10240 + woff, g_w2h + (size_t)rr * Hh + k0 + ca * 8);
            cpasync16(sb + 25600 + woff, g_w2l + (size_t)rr * Hh + k0 + ca * 8);
        }
        CP_COMMIT();
    };

    issue(0, 0);
    for (int s = 0; s < 24; s++) {
        if (s + 1 < 24) { issue(s + 1, (s + 1) & 1); CP_WAIT1(); }
        else CP_WAIT0();
        __syncthreads();
        const uint32_t* AH = (const uint32_t*)(dynsmem + (s & 1) * 40960);
        const uint32_t* AL = AH + 1280;
        const uint32_t* BH = AH + 2560;
        const uint32_t* BL = AH + 6400;
#pragma unroll
        for (int k16 = 0; k16 < 2; k16++) {
            int kw = k16 * 8;
            const uint32_t* APs[3] = {AH, AL, AH};
            const uint32_t* BPs[3] = {BH, BH, BL};
#pragma unroll
            for (int sp = 0; sp < 3; sp++) {
                uint32_t a[2][4], b[6][2];
#pragma unroll
                for (int mi = 0; mi < 2; mi++)
                    ldfragA(a[mi], APs[sp], wm0 + mi * 16, kw, g, tig);
#pragma unroll
                for (int ni = 0; ni < 6; ni++)
                    ldfragB(b[ni], BPs[sp], wn0 + ni * 8, kw, g, tig);
#pragma unroll
                for (int mi = 0; mi < 2; mi++)
#pragma unroll
                    for (int ni = 0; ni < 6; ni++)
                        mma16816(acc[mi][ni], a[mi], b[ni]);
            }
        }
        __syncthreads();
    }

    // epilogue: BN + direct store (channel pairs contiguous)
#pragma unroll
    for (int mi = 0; mi < 2; mi++)
#pragma unroll
        for (int ni = 0; ni < 6; ni++) {
            int m = wm0 + mi * 16 + g;
            int nn = wn0 + ni * 8 + tig * 2;
            float s0 = scS[nn], s1 = scS[nn + 1];
            float c0 = biS[nn], c1 = biS[nn + 1];
            float2 v0 = make_float2(fmaf(acc[mi][ni][0], s0, c0), fmaf(acc[mi][ni][1], s1, c1));
            float2 v1 = make_float2(fmaf(acc[mi][ni][2], s0, c0), fmaf(acc[mi][ni][3], s1, c1));
            *(float2*)(Y + (size_t)(t0 + m) * Cc + nn) = v0;
            *(float2*)(Y + (size_t)(t0 + m + 8) * Cc + nn) = v1;
        }
}

// ---------------------------------------------------------------------------
extern "C" void kernel_launch(void* const* d_in, const int* in_sizes, int n_in,
                              void* d_out, int out_size) {
    const float* x  = (const float*)d_in[0];
    const float* W1 = (const float*)d_in[1];
    const float* g1 = (const float*)d_in[2];
    const float* b1 = (const float*)d_in[3];
    const float* m1 = (const float*)d_in[4];
    const float* v1 = (const float*)d_in[5];
    const float* r  = (const float*)d_in[6];
    const float* im = (const float*)d_in[7];
    const float* rb = (const float*)d_in[8];
    const float* ib = (const float*)d_in[9];
    const float* W2 = (const float*)d_in[10];
    const float* g2 = (const float*)d_in[11];
    const float* b2 = (const float*)d_in[12];
    const float* m2 = (const float*)d_in[13];
    const float* v2 = (const float*)d_in[14];
    float* out = (float*)d_out;

    __nv_bfloat16 *xh, *xl, *w1h, *w1l, *w2h, *w2l;
    cudaGetSymbolAddress((void**)&xh,  g_xh);
    cudaGetSymbolAddress((void**)&xl,  g_xl);
    cudaGetSymbolAddress((void**)&w1h, g_w1h);
    cudaGetSymbolAddress((void**)&w1l, g_w1l);
    cudaGetSymbolAddress((void**)&w2h, g_w2h);
    cudaGetSymbolAddress((void**)&w2l, g_w2l);

    static bool attr_set = false;
    if (!attr_set) {
        cudaFuncSetAttribute(fc1_mma, cudaFuncAttributeMaxDynamicSharedMemorySize, 81920);
        cudaFuncSetAttribute(fc2_mma, cudaFuncAttributeMaxDynamicSharedMemorySize, 81920);
        attr_set = true;
    }

    conv_pair<<<1536, 256>>>(x,  xh,  xl,  1572864);
    conv_pair<<<144, 256>>>(W1, w1h, w1l, 36864);
    conv_pair<<<144, 256>>>(W2, w2h, w2l, 36864);
    fc1_mma<<<dim3(256, 6), 256, 81920>>>(g1, b1, m1, v1);
    fft_mix_kernel<<<Bb * Hh, 256>>>(r, im, rb, ib);
    transpose_split<<<dim3(128, 24, 8), dim3(32, 8)>>>();
    fc2_mma<<<512, 256, 81920>>>(g2, b2, m2, v2, out);
}

// round 16
// speedup vs baseline: 2.6445x; 1.3021x over previous
#include <cuda_runtime.h>
#include <cuda_bf16.h>
#include <math.h>
#include <cstdint>

#define EPSV 1e-5f

constexpr int Bb = 8;
constexpr int NT = 4096;   // tokens (FFT length)
constexpr int Cc = 192;    // input/output channels
constexpr int Hh = 768;    // hidden channels

// fp32 scratch (FFT works in place here)
__device__ float g_h1[25165824];            // [B, H, N]
// bf16 hi/lo operand buffers
__device__ __nv_bfloat16 g_xh[6291456],  g_xl[6291456];    // x  [B*N, C]
__device__ __nv_bfloat16 g_w1h[147456],  g_w1l[147456];    // W1 [H, C]
__device__ __nv_bfloat16 g_w2h[147456],  g_w2l[147456];    // W2 [C, H]
__device__ __nv_bfloat16 g_h2h[25165824], g_h2l[25165824]; // h  [B, N, H] transposed

// ===================== helpers =====================
__device__ __forceinline__ uint32_t smem_u32(const void* p) {
    uint32_t a;
    asm("{ .reg .u64 t; cvta.to.shared.u64 t, %1; cvt.u32.u64 %0, t; }" : "=r"(a) : "l"(p));
    return a;
}
__device__ __forceinline__ void cpasync16(uint32_t dst, const void* src) {
    asm volatile("cp.async.cg.shared.global [%0], [%1], 16;" :: "r"(dst), "l"(src));
}
#define CP_COMMIT() asm volatile("cp.async.commit_group;" ::: "memory")
#define CP_WAIT1() asm volatile("cp.async.wait_group 1;" ::: "memory")
#define CP_WAIT0() asm volatile("cp.async.wait_group 0;" ::: "memory")

__device__ __forceinline__ void mma16816(float* c, const uint32_t* a, const uint32_t* b) {
    asm volatile(
        "mma.sync.aligned.m16n8k16.row.col.f32.bf16.bf16.f32 "
        "{%0,%1,%2,%3}, {%4,%5,%6,%7}, {%8,%9}, {%0,%1,%2,%3};"
        : "+f"(c[0]), "+f"(c[1]), "+f"(c[2]), "+f"(c[3])
        : "r"(a[0]), "r"(a[1]), "r"(a[2]), "r"(a[3]), "r"(b[0]), "r"(b[1]));
}

union BfPack { __nv_bfloat16 b[2]; uint32_t u; };
__device__ __forceinline__ void split_pair(float f0, float f1, uint32_t& hi, uint32_t& lo) {
    BfPack H, L;
    H.b[0] = __float2bfloat16(f0);
    H.b[1] = __float2bfloat16(f1);
    L.b[0] = __float2bfloat16(f0 - __bfloat162float(H.b[0]));
    L.b[1] = __float2bfloat16(f1 - __bfloat162float(H.b[1]));
    hi = H.u; lo = L.u;
}

// fragment loads from padded K-major bf16 tiles (row stride 20 words)
__device__ __forceinline__ void ldfragA(uint32_t* a, const uint32_t* S, int r0, int kw, int g, int tig) {
    a[0] = S[(r0 + g) * 20 + kw + tig];
    a[1] = S[(r0 + g + 8) * 20 + kw + tig];
    a[2] = S[(r0 + g) * 20 + kw + 4 + tig];
    a[3] = S[(r0 + g + 8) * 20 + kw + 4 + tig];
}
__device__ __forceinline__ void ldfragB(uint32_t* b, const uint32_t* S, int n0, int kw, int g, int tig) {
    b[0] = S[(n0 + g) * 20 + kw + tig];
    b[1] = S[(n0 + g) * 20 + kw + 4 + tig];
}

// ---------------------------------------------------------------------------
// prepass: split fp32 -> bf16 hi/lo (vectorized, grid-stride)
// ---------------------------------------------------------------------------
__global__ __launch_bounds__(256) void conv_pair(
    const float* __restrict__ s, __nv_bfloat16* __restrict__ h,
    __nv_bfloat16* __restrict__ l, int n4)
{
    for (int i = blockIdx.x * blockDim.x + threadIdx.x; i < n4; i += gridDim.x * blockDim.x) {
        float4 v = ((const float4*)s)[i];
        uint32_t h0, h1, l0, l1;
        split_pair(v.x, v.y, h0, l0);
        split_pair(v.z, v.w, h1, l1);
        ((uint2*)h)[i] = make_uint2(h0, h1);
        ((uint2*)l)[i] = make_uint2(l0, l1);
    }
}

// ---------------------------------------------------------------------------
// fc1: h[b,hc,n] = relu(BN(X @ W1^T)). Tile 128 tok x 128 hc, K=192.
// cp.async double-buffered bf16 stages; 8 warps 2(M=64) x 4(N=32).
// ---------------------------------------------------------------------------
__global__ __launch_bounds__(256, 2) void fc1_mma(
    const float* __restrict__ g1, const float* __restrict__ b1,
    const float* __restrict__ m1, const float* __restrict__ v1)
{
    extern __shared__ char dynsmem[];
    const uint32_t sbase = smem_u32(dynsmem);
    __shared__ float scS[128], biS[128];

    const int tid = threadIdx.x, wid = tid >> 5, lane = tid & 31;
    const int g = lane >> 2, tig = lane & 3;
    const int t0 = blockIdx.x * 128;    // token base (flat 32768)
    const int n0 = blockIdx.y * 128;    // hc base
    const int wm0 = (wid >> 2) * 64;
    const int wn0 = (wid & 3) * 32;

    if (tid < 128) {
        int hc = n0 + tid;
        float s = g1[hc] * rsqrtf(v1[hc] + EPSV);
        scS[tid] = s;
        biS[tid] = b1[hc] - m1[hc] * s;
    }

    float acc[4][4][4];
#pragma unroll
    for (int mi = 0; mi < 4; mi++)
#pragma unroll
        for (int ni = 0; ni < 4; ni++)
#pragma unroll
            for (int q = 0; q < 4; q++) acc[mi][ni][q] = 0.f;

    const int r = tid >> 2, c = tid & 3;
    auto issue = [&](int s, int bi) {
        uint32_t sb = sbase + bi * 40960;
        int k0 = s * 32;
#pragma unroll
        for (int it = 0; it < 2; it++) {
            int rr = r + it * 64;
            uint32_t woff = (rr * 20 + c * 4) * 4;
            cpasync16(sb + woff,         g_xh + (size_t)(t0 + rr) * Cc + k0 + c * 8);
            cpasync16(sb + 10240 + woff, g_xl + (size_t)(t0 + rr) * Cc + k0 + c * 8);
            cpasync16(sb + 20480 + woff, g_w1h + (size_t)(n0 + rr) * Cc + k0 + c * 8);
            cpasync16(sb + 30720 + woff, g_w1l + (size_t)(n0 + rr) * Cc + k0 + c * 8);
        }
        CP_COMMIT();
    };

    issue(0, 0);
    for (int s = 0; s < 6; s++) {
        if (s + 1 < 6) { issue(s + 1, (s + 1) & 1); CP_WAIT1(); }
        else CP_WAIT0();
        __syncthreads();
        const uint32_t* AH = (const uint32_t*)(dynsmem + (s & 1) * 40960);
        const uint32_t* AL = AH + 2560;
        const uint32_t* BH = AH + 5120;
        const uint32_t* BL = AH + 7680;
#pragma unroll
        for (int k16 = 0; k16 < 2; k16++) {
            int kw = k16 * 8;
            const uint32_t* APs[3] = {AH, AL, AH};
            const uint32_t* BPs[3] = {BH, BH, BL};
#pragma unroll
            for (int sp = 0; sp < 3; sp++) {
                uint32_t a[4][4], b[4][2];
#pragma unroll
                for (int mi = 0; mi < 4; mi++)
                    ldfragA(a[mi], APs[sp], wm0 + mi * 16, kw, g, tig);
#pragma unroll
                for (int ni = 0; ni < 4; ni++)
                    ldfragB(b[ni], BPs[sp], wn0 + ni * 8, kw, g, tig);
#pragma unroll
                for (int mi = 0; mi < 4; mi++)
#pragma unroll
                    for (int ni = 0; ni < 4; ni++)
                        mma16816(acc[mi][ni], a[mi], b[ni]);
            }
        }
        __syncthreads();
    }

    // epilogue: BN+relu, stage [n][m] halves through smem, coalesced [B,H,N] store
    const int b = t0 >> 12;
    const int tn0 = t0 & 4095;
    float* Cst = (float*)dynsmem;
    const int myh = (wid & 3) >> 1;
    for (int h = 0; h < 2; h++) {
        if (myh == h) {
#pragma unroll
            for (int mi = 0; mi < 4; mi++)
#pragma unroll
                for (int ni = 0; ni < 4; ni++) {
                    int m = wm0 + mi * 16 + g;
                    int nn = wn0 + ni * 8 + tig * 2;
                    int nl = nn - h * 64;
                    float s0 = scS[nn], s1 = scS[nn + 1];
                    float c0 = biS[nn], c1 = biS[nn + 1];
                    Cst[nl * 132 + m]            = fmaxf(fmaf(acc[mi][ni][0], s0, c0), 0.f);
                    Cst[(nl + 1) * 132 + m]      = fmaxf(fmaf(acc[mi][ni][1], s1, c1), 0.f);
                    Cst[nl * 132 + m + 8]        = fmaxf(fmaf(acc[mi][ni][2], s0, c0), 0.f);
                    Cst[(nl + 1) * 132 + m + 8]  = fmaxf(fmaf(acc[mi][ni][3], s1, c1), 0.f);
                }
        }
        __syncthreads();
        {
            int n = tid >> 2, mseg = (tid & 3) * 32;
            float* dst = g_h1 + (size_t)(b * Hh + n0 + h * 64 + n) * NT + tn0 + mseg;
            const float* srcr = &Cst[n * 132 + mseg];
#pragma unroll
            for (int q = 0; q < 32; q += 4)
                *(float4*)(dst + q) = *(const float4*)(srcr + q);
        }
        __syncthreads();
    }
}

// ---------------------------------------------------------------------------
// FFT(4096) on PACKED pairs of real rows -> mix -> IFFT, in place on g_h1.
// z = row0 + i*row1, one forward FFT. Spectra live in base-4 digit-reversed
// order; partner bin N-k sits at position rev4((N-rev4(p)) & (N-1)).
// Separation, per-channel mix+relu, and conjugate-symmetrization (which makes
// the inverse output exactly real per component) are all local to each
// unordered position pair {p, p'}.
// ---------------------------------------------------------------------------
__device__ __forceinline__ float2 cmulf(float2 a, float2 b) {
    return make_float2(a.x * b.x - a.y * b.y, a.x * b.y + a.y * b.x);
}
__device__ __forceinline__ float2 cadd(float2 a, float2 b) { return make_float2(a.x + b.x, a.y + b.y); }
__device__ __forceinline__ float2 csub(float2 a, float2 b) { return make_float2(a.x - b.x, a.y - b.y); }

#define SWZ(i) ((i) ^ (((i) >> 4) & 15))

__device__ __forceinline__ int rev4(int p) {
    return ((p & 0x003) << 10) | ((p & 0x00C) << 6) | ((p & 0x030) << 2)
         | ((p & 0x0C0) >> 2)  | ((p & 0x300) >> 6) | ((p & 0xC00) >> 10);
}

__device__ __forceinline__ float2 twid(const float2* __restrict__ T, int m) {
    float2 w = T[m & 1023];
    int q = m >> 10;
    if (q == 1) return make_float2(w.y, -w.x);
    if (q == 2) return make_float2(-w.x, -w.y);
    return w;
}
__device__ __forceinline__ float2 twidc(const float2* __restrict__ T, int m) {
    float2 w = twid(T, m);
    return make_float2(w.x, -w.y);
}
__device__ __forceinline__ float2 mixf(float2 F, float rd, float id, float rb, float ib) {
    return make_float2(fmaxf(fmaf(rd, F.x, fmaf(-id, F.y, rb)), 0.f),
                       fmaxf(fmaf(rd, F.y, fmaf(id, F.x, ib)), 0.f));
}

__global__ __launch_bounds__(256) void fft_mix_kernel(
    const float* __restrict__ R, const float* __restrict__ Im,
    const float* __restrict__ RB, const float* __restrict__ IB)
{
    __shared__ float2 S[4096];
    __shared__ float2 T[1024];

    const int tid = threadIdx.x;
    const int row0 = blockIdx.x * 2;            // rows row0, row0+1 (same batch: Hh even)
    const int hc0 = row0 % Hh, hc1 = hc0 + 1;
    float* d0 = g_h1 + (size_t)row0 * NT;
    float* d1 = d0 + NT;

    for (int m = tid; m < 1024; m += 256) {
        float s, c;
        sincospif(-(float)m / 2048.0f, &s, &c);
        T[m] = make_float2(c, s);
    }
    for (int t = tid; t < 4096; t += 256)
        S[SWZ(t)] = make_float2(d0[t], d1[t]);
    __syncthreads();

    // ---- forward: 3 fused radix-16 passes (DIF) ----
#pragma unroll
    for (int ls = 12; ls >= 4; ls -= 4) {
        const int Q  = 1 << (ls - 2);
        const int Q4 = 1 << (ls - 4);
        const int stepw  = 1 << (12 - ls);
        const int stepw4 = stepw << 2;
        const int j = tid & (Q4 - 1);
        const int base = (tid >> (ls - 4)) << ls;

        float2 X[4][4];
#pragma unroll
        for (int q = 0; q < 4; q++)
#pragma unroll
            for (int p = 0; p < 4; p++)
                X[q][p] = S[SWZ(base + j + p * Q4 + q * Q)];

#pragma unroll
        for (int p = 0; p < 4; p++) {
            float2 a = X[0][p], b = X[1][p], c = X[2][p], d = X[3][p];
            float2 apc = cadd(a, c), amc = csub(a, c);
            float2 bpd = cadd(b, d), bmd = csub(b, d);
            int e = (j + p * Q4) * stepw;
            X[0][p] = cadd(apc, bpd);
            X[1][p] = cmulf(twid(T, e),     make_float2(amc.x + bmd.y, amc.y - bmd.x));
            X[2][p] = cmulf(twid(T, 2 * e), csub(apc, bpd));
            X[3][p] = cmulf(twid(T, 3 * e), make_float2(amc.x - bmd.y, amc.y + bmd.x));
        }
        {
            int e2 = j * stepw4;
            float2 w1 = twid(T, e2), w2 = twid(T, 2 * e2), w3 = twid(T, 3 * e2);
#pragma unroll
            for (int q = 0; q < 4; q++) {
                float2 a = X[q][0], b = X[q][1], c = X[q][2], d = X[q][3];
                float2 apc = cadd(a, c), amc = csub(a, c);
                float2 bpd = cadd(b, d), bmd = csub(b, d);
                X[q][0] = cadd(apc, bpd);
                X[q][1] = cmulf(w1, make_float2(amc.x + bmd.y, amc.y - bmd.x));
                X[q][2] = cmulf(w2, csub(apc, bpd));
                X[q][3] = cmulf(w3, make_float2(amc.x - bmd.y, amc.y + bmd.x));
            }
        }
        __syncthreads();
#pragma unroll
        for (int q = 0; q < 4; q++)
#pragma unroll
            for (int p = 0; p < 4; p++)
                S[SWZ(base + j + p * Q4 + q * Q)] = X[q][p];
        __syncthreads();
    }

    // ---- separate packed spectra, mix both channels, re-symmetrize, repack ----
    {
        const float rd0 = R[hc0 * (Hh + 1)], id0 = Im[hc0 * (Hh + 1)];
        const float rb0 = RB[hc0], ib0 = IB[hc0];
        const float rd1 = R[hc1 * (Hh + 1)], id1 = Im[hc1 * (Hh + 1)];
        const float rb1 = RB[hc1], ib1 = IB[hc1];
        const float inv = 0.015625f;       // ortho 1/sqrt(4096)
        for (int t = tid; t < 4096; t += 256) {
            int k = rev4(t);
            int pp = rev4((4096 - k) & 4095);
            if (pp < t) continue;          // each unordered pair handled once
            float2 za = S[SWZ(t)], zb = S[SWZ(pp)];
            za.x *= inv; za.y *= inv; zb.x *= inv; zb.y *= inv;
            // Fa(k), Fb(k) from u=za, conj(zb); Fa(N-k), Fb(N-k) symmetric
            float2 Fa_k = make_float2(0.5f * (za.x + zb.x), 0.5f * (za.y - zb.y));
            float2 Fb_k = make_float2(0.5f * (za.y + zb.y), 0.5f * (zb.x - za.x));
            float2 Fa_p = make_float2(0.5f * (zb.x + za.x), 0.5f * (zb.y - za.y));
            float2 Fb_p = make_float2(0.5f * (zb.y + za.y), 0.5f * (za.x - zb.x));
            float2 Xa_k = mixf(Fa_k, rd0, id0, rb0, ib0);
            float2 Xa_p = mixf(Fa_p, rd0, id0, rb0, ib0);
            float2 Xb_k = mixf(Fb_k, rd1, id1, rb1, ib1);
            float2 Xb_p = mixf(Fb_p, rd1, id1, rb1, ib1);
            // conjugate-symmetrize each channel -> inverse output is exactly real
            float2 Sa_k = make_float2(0.5f * (Xa_k.x + Xa_p.x), 0.5f * (Xa_k.y - Xa_p.y));
            float2 Sa_p = make_float2(0.5f * (Xa_p.x + Xa_k.x), 0.5f * (Xa_p.y - Xa_k.y));
            float2 Sb_k = make_float2(0.5f * (Xb_k.x + Xb_p.x), 0.5f * (Xb_k.y - Xb_p.y));
            float2 Sb_p = make_float2(0.5f * (Xb_p.x + Xb_k.x), 0.5f * (Xb_p.y - Xb_k.y));
            S[SWZ(t)]  = make_float2(Sa_k.x - Sb_k.y, Sa_k.y + Sb_k.x);
            S[SWZ(pp)] = make_float2(Sa_p.x - Sb_p.y, Sa_p.y + Sb_p.x);
        }
    }
    __syncthreads();

    // ---- inverse: 3 fused passes (exact mirror) ----
#pragma unroll
    for (int ls = 4; ls <= 12; ls += 4) {
        const int Q  = 1 << (ls - 2);
        const int Q4 = 1 << (ls - 4);
        const int stepw  = 1 << (12 - ls);
        const int stepw4 = stepw << 2;
        const int j = tid & (Q4 - 1);
        const int base = (tid >> (ls - 4)) << ls;

        float2 X[4][4];
#pragma unroll
        for (int q = 0; q < 4; q++)
#pragma unroll
            for (int p = 0; p < 4; p++)
                X[q][p] = S[SWZ(base + j + p * Q4 + q * Q)];

        {
            int e2 = j * stepw4;
            float2 w1 = twidc(T, e2), w2 = twidc(T, 2 * e2), w3 = twidc(T, 3 * e2);
#pragma unroll
            for (int q = 0; q < 4; q++) {
                float2 a = X[q][0];
                float2 b = cmulf(w1, X[q][1]);
                float2 c = cmulf(w2, X[q][2]);
                float2 d = cmulf(w3, X[q][3]);
                float2 apc = cadd(a, c), amc = csub(a, c);
                float2 bpd = cadd(b, d), bmd = csub(b, d);
                X[q][0] = cadd(apc, bpd);
                X[q][1] = make_float2(amc.x - bmd.y, amc.y + bmd.x);
                X[q][2] = csub(apc, bpd);
                X[q][3] = make_float2(amc.x + bmd.y, amc.y - bmd.x);
            }
        }
#pragma unroll
        for (int p = 0; p < 4; p++) {
            int e = (j + p * Q4) * stepw;
            float2 a = X[0][p];
            float2 b = cmulf(twidc(T, e),     X[1][p]);
            float2 c = cmulf(twidc(T, 2 * e), X[2][p]);
            float2 d = cmulf(twidc(T, 3 * e), X[3][p]);
            float2 apc = cadd(a, c), amc = csub(a, c);
            float2 bpd = cadd(b, d), bmd = csub(b, d);
            X[0][p] = cadd(apc, bpd);
            X[1][p] = make_float2(amc.x - bmd.y, amc.y + bmd.x);
            X[2][p] = csub(apc, bpd);
            X[3][p] = make_float2(amc.x + bmd.y, amc.y - bmd.x);
        }
        __syncthreads();
#pragma unroll
        for (int q = 0; q < 4; q++)
#pragma unroll
            for (int p = 0; p < 4; p++)
                S[SWZ(base + j + p * Q4 + q * Q)] = X[q][p];
        __syncthreads();
    }

    const float inv = 0.015625f;
    for (int t = tid; t < 4096; t += 256) {
        float2 v = S[SWZ(t)];
        d0[t] = v.x * inv;
        d1[t] = v.y * inv;
    }
}

// ---------------------------------------------------------------------------
// transpose+split: g_h1 [B,H,N] fp32 -> g_h2h/g_h2l [B,N,H] bf16
// ---------------------------------------------------------------------------
__global__ __launch_bounds__(256) void transpose_split()
{
    __shared__ float t[32][33];
    const int b = blockIdx.z;
    const int n0 = blockIdx.x * 32, h0 = blockIdx.y * 32;
    const float* src = g_h1 + (size_t)b * Hh * NT;
    const size_t dbase = (size_t)b * NT * Hh;
    const int tx = threadIdx.x, ty = threadIdx.y;
#pragma unroll
    for (int j = 0; j < 32; j += 8)
        t[ty + j][tx] = src[(size_t)(h0 + ty + j) * NT + n0 + tx];
    __syncthreads();
#pragma unroll
    for (int j = 0; j < 32; j += 8) {
        float v = t[tx][ty + j];
        __nv_bfloat16 hi = __float2bfloat16(v);
        __nv_bfloat16 lo = __float2bfloat16(v - __bfloat162float(hi));
        size_t idx = dbase + (size_t)(n0 + ty + j) * Hh + h0 + tx;
        g_h2h[idx] = hi;
        g_h2l[idx] = lo;
    }
}

// ---------------------------------------------------------------------------
// fc2: y[b,n,c] = BN(h_t @ W2^T). Tile 64 tok x 192 c, K=768 (24 stages).
// cp.async double-buffered; 8 warps 2(M=32) x 4(N=48).
// ---------------------------------------------------------------------------
__global__ __launch_bounds__(256, 2) void fc2_mma(
    const float* __restrict__ g2, const float* __restrict__ b2,
    const float* __restrict__ m2, const float* __restrict__ v2,
    float* __restrict__ Y)
{
    extern __shared__ char dynsmem[];
    const uint32_t sbase = smem_u32(dynsmem);
    __shared__ float scS[192], biS[192];

    const int tid = threadIdx.x, wid = tid >> 5, lane = tid & 31;
    const int g = lane >> 2, tig = lane & 3;
    const int t0 = blockIdx.x * 64;
    const int wm0 = (wid >> 2) * 32;
    const int wn0 = (wid & 3) * 48;

    if (tid < 192) {
        float s = g2[tid] * rsqrtf(v2[tid] + EPSV);
        scS[tid] = s;
        biS[tid] = b2[tid] - m2[tid] * s;
    }

    float acc[2][6][4];
#pragma unroll
    for (int mi = 0; mi < 2; mi++)
#pragma unroll
        for (int ni = 0; ni < 6; ni++)
#pragma unroll
            for (int q = 0; q < 4; q++) acc[mi][ni][q] = 0.f;

    const int ra = tid >> 2, ca = tid & 3;
    auto issue = [&](int s, int bi) {
        uint32_t sb = sbase + bi * 40960;
        int k0 = s * 32;
        {
            uint32_t woff = (ra * 20 + ca * 4) * 4;
            cpasync16(sb + woff,        g_h2h + (size_t)(t0 + ra) * Hh + k0 + ca * 8);
            cpasync16(sb + 5120 + woff, g_h2l + (size_t)(t0 + ra) * Hh + k0 + ca * 8);
        }
#pragma unroll
        for (int it = 0; it < 3; it++) {
            int rr = ra + it * 64;
            uint32_t woff = (rr * 20 + ca * 4) * 4;
            cpasync16(sb + 10240 + woff, g_w2h + (size_t)rr * Hh + k0 + ca * 8);
            cpasync16(sb + 25600 + woff, g_w2l + (size_t)rr * Hh + k0 + ca * 8);
        }
        CP_COMMIT();
    };

    issue(0, 0);
    for (int s = 0; s < 24; s++) {
        if (s + 1 < 24) { issue(s + 1, (s + 1) & 1); CP_WAIT1(); }
        else CP_WAIT0();
        __syncthreads();
        const uint32_t* AH = (const uint32_t*)(dynsmem + (s & 1) * 40960);
        const uint32_t* AL = AH + 1280;
        const uint32_t* BH = AH + 2560;
        const uint32_t* BL = AH + 6400;
#pragma unroll
        for (int k16 = 0; k16 < 2; k16++) {
            int kw = k16 * 8;
            const uint32_t* APs[3] = {AH, AL, AH};
            const uint32_t* BPs[3] = {BH, BH, BL};
#pragma unroll
            for (int sp = 0; sp < 3; sp++) {
                uint32_t a[2][4], b[6][2];
#pragma unroll
                for (int mi = 0; mi < 2; mi++)
                    ldfragA(a[mi], APs[sp], wm0 + mi * 16, kw, g, tig);
#pragma unroll
                for (int ni = 0; ni < 6; ni++)
                    ldfragB(b[ni], BPs[sp], wn0 + ni * 8, kw, g, tig);
#pragma unroll
                for (int mi = 0; mi < 2; mi++)
#pragma unroll
                    for (int ni = 0; ni < 6; ni++)
                        mma16816(acc[mi][ni], a[mi], b[ni]);
            }
        }
        __syncthreads();
    }

#pragma unroll
    for (int mi = 0; mi < 2; mi++)
#pragma unroll
        for (int ni = 0; ni < 6; ni++) {
            int m = wm0 + mi * 16 + g;
            int nn = wn0 + ni * 8 + tig * 2;
            float s0 = scS[nn], s1 = scS[nn + 1];
            float c0 = biS[nn], c1 = biS[nn + 1];
            float2 v0 = make_float2(fmaf(acc[mi][ni][0], s0, c0), fmaf(acc[mi][ni][1], s1, c1));
            float2 v1 = make_float2(fmaf(acc[mi][ni][2], s0, c0), fmaf(acc[mi][ni][3], s1, c1));
            *(float2*)(Y + (size_t)(t0 + m) * Cc + nn) = v0;
            *(float2*)(Y + (size_t)(t0 + m + 8) * Cc + nn) = v1;
        }
}

// ---------------------------------------------------------------------------
extern "C" void kernel_launch(void* const* d_in, const int* in_sizes, int n_in,
                              void* d_out, int out_size) {
    const float* x  = (const float*)d_in[0];
    const float* W1 = (const float*)d_in[1];
    const float* g1 = (const float*)d_in[2];
    const float* b1 = (const float*)d_in[3];
    const float* m1 = (const float*)d_in[4];
    const float* v1 = (const float*)d_in[5];
    const float* r  = (const float*)d_in[6];
    const float* im = (const float*)d_in[7];
    const float* rb = (const float*)d_in[8];
    const float* ib = (const float*)d_in[9];
    const float* W2 = (const float*)d_in[10];
    const float* g2 = (const float*)d_in[11];
    const float* b2 = (const float*)d_in[12];
    const float* m2 = (const float*)d_in[13];
    const float* v2 = (const float*)d_in[14];
    float* out = (float*)d_out;

    __nv_bfloat16 *xh, *xl, *w1h, *w1l, *w2h, *w2l;
    cudaGetSymbolAddress((void**)&xh,  g_xh);
    cudaGetSymbolAddress((void**)&xl,  g_xl);
    cudaGetSymbolAddress((void**)&w1h, g_w1h);
    cudaGetSymbolAddress((void**)&w1l, g_w1l);
    cudaGetSymbolAddress((void**)&w2h, g_w2h);
    cudaGetSymbolAddress((void**)&w2l, g_w2l);

    static bool attr_set = false;
    if (!attr_set) {
        cudaFuncSetAttribute(fc1_mma, cudaFuncAttributeMaxDynamicSharedMemorySize, 81920);
        cudaFuncSetAttribute(fc2_mma, cudaFuncAttributeMaxDynamicSharedMemorySize, 81920);
        attr_set = true;
    }

    conv_pair<<<1536, 256>>>(x,  xh,  xl,  1572864);
    conv_pair<<<144, 256>>>(W1, w1h, w1l, 36864);
    conv_pair<<<144, 256>>>(W2, w2h, w2l, 36864);
    fc1_mma<<<dim3(256, 6), 256, 81920>>>(g1, b1, m1, v1);
    fft_mix_kernel<<<Bb * Hh / 2, 256>>>(r, im, rb, ib);
    transpose_split<<<dim3(128, 24, 8), dim3(32, 8)>>>();
    fc2_mma<<<512, 256, 81920>>>(g2, b2, m2, v2, out);
}